// round 6
// baseline (speedup 1.0000x reference)
#include <cuda_runtime.h>
#include <cuda_bf16.h>
#include <math.h>

#define THR 0.005f
#define EPSI 1e-5f
#define NBATCH 4
#define NNODE 4096
#define NCH 64
#define SP 136   // padded bf16 row stride for B smem tile

typedef unsigned long long ull;
typedef unsigned int uint;

// ---------------- device scratch ----------------
__device__ __align__(16) float g_xt[NBATCH * NNODE * NCH];     // x transposed [b][n][c]
__device__ __align__(16) float g_snorm[NBATCH * NNODE];
__device__ __align__(16) float g_dinv[NBATCH * NNODE];
__device__ __align__(16) unsigned g_adjT[NBATCH * 128 * NNODE];       // bits [b][word_m][n]
__device__ __align__(16) unsigned short g_xs [NBATCH * NNODE * 128];  // bf16 split layer0 in
__device__ __align__(16) unsigned short g_xs2[NBATCH * NNODE * 128];  // bf16 split layer1 in

// ---------------- helpers ----------------
__device__ __forceinline__ void fma2(ull& d, ull a, ull b) {
    asm("fma.rn.f32x2 %0, %1, %2, %0;" : "+l"(d) : "l"(a), "l"(b));
}
__device__ __forceinline__ ull pack2(float x) {
    ull r; asm("mov.b64 %0, {%1, %1};" : "=l"(r) : "f"(x)); return r;
}
union F2U { ull u; float2 f; };

__device__ __forceinline__ uint bfpair(uint u) {
    return ((u & 1u) ? 0x3F80u : 0u) | ((u & 2u) ? 0x3F800000u : 0u);
}

// ---------------- transpose & norms ----------------
__global__ void k_transpose(const float* __restrict__ x) {
    __shared__ float t[32][33];
    int b = blockIdx.z, c0 = blockIdx.y * 32, n0 = blockIdx.x * 32;
    int tx = threadIdx.x, ty = threadIdx.y;
    const float* xp = x + ((b * 64 + c0) * NNODE) + n0;
    #pragma unroll
    for (int i = ty; i < 32; i += 8) t[i][tx] = xp[i * NNODE + tx];
    __syncthreads();
    float* op = g_xt + ((b * NNODE + n0) * 64) + c0;
    #pragma unroll
    for (int i = ty; i < 32; i += 8) op[i * 64 + tx] = t[tx][i];
}

__global__ void k_norm() {
    int i = blockIdx.x * 256 + threadIdx.x;
    if (i >= NBATCH * NNODE) return;
    const float4* p = (const float4*)(g_xt + (size_t)i * 64);
    float s = 0.f;
    #pragma unroll
    for (int j = 0; j < 16; j++) {
        float4 v = p[j];
        s += v.x * v.x + v.y * v.y + v.z * v.z + v.w * v.w;
    }
    g_snorm[i] = sqrtf(s);
}

// ---------------- Gram + threshold -> adjacency bits ----------------
// Block: 256 threads = 8 warps. Block tile 256n x 128m. Warp = 32n strip x 128m.
// Thread tile 8n x 16m (acc[8][8] fp32x2). K staged in 4 chunks of 16.
// Triangular rectangular tiles: bi (256n) 0..15, bj (128m) 0..31, bj >= 2bi.
// Symmetric threshold val > THR*(sn*sm) -> duplicate writes bitwise identical.
__global__ void __launch_bounds__(256) k_gram(const float* __restrict__ x) {
    __shared__ __align__(16) float As[16][256];
    __shared__ __align__(16) float Bs[16][128];
    __shared__ float sns[256], sms[128];

    int b = blockIdx.z;
    int xid = blockIdx.x;
    int bi = (int)((33.0f - sqrtf(1089.0f - 4.0f * (float)xid)) * 0.5f);
    if (bi > 15) bi = 15;
    if (bi < 0) bi = 0;
    while (bi < 15 && (bi + 1) * (33 - (bi + 1)) <= xid) bi++;
    while (bi > 0 && bi * (33 - bi) > xid) bi--;
    int bj = 2 * bi + (xid - bi * (33 - bi));
    int n0 = bi * 256, m0 = bj * 128;

    int t = threadIdx.x;
    sns[t] = g_snorm[b * NNODE + n0 + t];
    if (t < 128) sms[t] = g_snorm[b * NNODE + m0 + t];

    int w = t >> 5, lane = t & 31;
    int r = lane >> 3, c = lane & 7;
    int nb = w * 32 + r * 8;

    ull acc[8][8];
    #pragma unroll
    for (int i = 0; i < 8; i++)
        #pragma unroll
        for (int j = 0; j < 8; j++) acc[i][j] = 0ULL;

    const float* xa = x + (size_t)(b * 64) * NNODE;

    // staging maps
    int a_row[4], a_c4[4];
    #pragma unroll
    for (int i = 0; i < 4; i++) { int f4 = t + i * 256; a_row[i] = f4 >> 6; a_c4[i] = f4 & 63; }
    int b_row[2], b_c4[2];
    #pragma unroll
    for (int i = 0; i < 2; i++) { int f4 = t + i * 256; b_row[i] = f4 >> 5; b_c4[i] = f4 & 31; }

    float4 pA[4], pB[2];
    #pragma unroll
    for (int i = 0; i < 4; i++)
        pA[i] = *(const float4*)(xa + (size_t)a_row[i] * NNODE + n0 + a_c4[i] * 4);
    #pragma unroll
    for (int i = 0; i < 2; i++)
        pB[i] = *(const float4*)(xa + (size_t)b_row[i] * NNODE + m0 + b_c4[i] * 4);

    for (int kc = 0; kc < 4; kc++) {
        __syncthreads();
        #pragma unroll
        for (int i = 0; i < 4; i++) *(float4*)&As[a_row[i]][a_c4[i] * 4] = pA[i];
        #pragma unroll
        for (int i = 0; i < 2; i++) *(float4*)&Bs[b_row[i]][b_c4[i] * 4] = pB[i];
        __syncthreads();
        if (kc < 3) {
            int kb = (kc + 1) * 16;
            #pragma unroll
            for (int i = 0; i < 4; i++)
                pA[i] = *(const float4*)(xa + (size_t)(kb + a_row[i]) * NNODE + n0 + a_c4[i] * 4);
            #pragma unroll
            for (int i = 0; i < 2; i++)
                pB[i] = *(const float4*)(xa + (size_t)(kb + b_row[i]) * NNODE + m0 + b_c4[i] * 4);
        }
        #pragma unroll
        for (int k = 0; k < 16; k++) {
            float4 a0 = *(const float4*)&As[k][nb];
            float4 a1 = *(const float4*)&As[k][nb + 4];
            ulonglong2 b0 = *(const ulonglong2*)&Bs[k][c * 4];
            ulonglong2 b1 = *(const ulonglong2*)&Bs[k][c * 4 + 32];
            ulonglong2 b2 = *(const ulonglong2*)&Bs[k][c * 4 + 64];
            ulonglong2 b3 = *(const ulonglong2*)&Bs[k][c * 4 + 96];
            float av[8] = {a0.x, a0.y, a0.z, a0.w, a1.x, a1.y, a1.z, a1.w};
            #pragma unroll
            for (int i = 0; i < 8; i++) {
                ull a2 = pack2(av[i]);
                fma2(acc[i][0], a2, b0.x); fma2(acc[i][1], a2, b0.y);
                fma2(acc[i][2], a2, b1.x); fma2(acc[i][3], a2, b1.y);
                fma2(acc[i][4], a2, b2.x); fma2(acc[i][5], a2, b2.y);
                fma2(acc[i][6], a2, b3.x); fma2(acc[i][7], a2, b3.y);
            }
        }
    }

    // ---- threshold + both-orientation bit packing ----
    float smv[16];
    #pragma unroll
    for (int idx = 0; idx < 16; idx++)
        smv[idx] = sms[c * 4 + 32 * (idx >> 2) + (idx & 3)];

    uint bytesT[16];
    #pragma unroll
    for (int idx = 0; idx < 16; idx++) bytesT[idx] = 0u;

    int gnbase = n0 + nb;
    #pragma unroll
    for (int i = 0; i < 8; i++) {
        float sni = sns[nb + i];
        uint cond[16];
        #pragma unroll
        for (int j = 0; j < 8; j++) {
            F2U u; u.u = acc[i][j];
            cond[2 * j]     = (u.f.x > THR * (sni * smv[2 * j]))     ? 1u : 0u;
            cond[2 * j + 1] = (u.f.y > THR * (sni * smv[2 * j + 1])) ? 1u : 0u;
        }
        #pragma unroll
        for (int idx = 0; idx < 16; idx++) bytesT[idx] |= cond[idx] << i;
        #pragma unroll
        for (int s = 0; s < 4; s++) {
            uint v = (cond[4 * s] | (cond[4 * s + 1] << 1) |
                      (cond[4 * s + 2] << 2) | (cond[4 * s + 3] << 3)) << (c * 4);
            v |= __shfl_xor_sync(0xffffffffu, v, 1);
            v |= __shfl_xor_sync(0xffffffffu, v, 2);
            v |= __shfl_xor_sync(0xffffffffu, v, 4);
            if (c == 0)
                g_adjT[((size_t)b * 128 + (m0 >> 5) + s) * NNODE + (gnbase + i)] = v;
        }
    }
    int nw = (n0 + w * 32) >> 5;
    #pragma unroll
    for (int idx = 0; idx < 16; idx++) {
        uint v = bytesT[idx] << (r * 8);
        v |= __shfl_xor_sync(0xffffffffu, v, 8);
        v |= __shfl_xor_sync(0xffffffffu, v, 16);
        if (r == 0) {
            int mg = m0 + c * 4 + 32 * (idx >> 2) + (idx & 3);
            g_adjT[((size_t)b * 128 + nw) * NNODE + mg] = v;
        }
    }
}

// ---------------- degree -> dinv ----------------
__global__ void k_deg() {
    int i = blockIdx.x * 128 + threadIdx.x;   // 128 blocks x 128 thr = 16384
    int b = i >> 12, nl = i & 4095;
    const unsigned* p = g_adjT + (size_t)b * 128 * NNODE + nl;
    int cdeg = 0;
    #pragma unroll 8
    for (int w = 0; w < 128; w++) cdeg += __popc(p[(size_t)w * NNODE]);
    g_dinv[i] = 1.0f / sqrtf((float)cdeg);
}

// ---------------- split (layer0 input): xs = bf16_split(g_xt * dinv) ----------------
__global__ void k_split() {
    int i = blockIdx.x * 256 + threadIdx.x;   // 262144 quads
    int node = i >> 4, c4 = (i & 15) * 4;
    float d = g_dinv[node];
    float4 v = *(const float4*)(g_xt + (size_t)node * 64 + c4);
    v.x *= d; v.y *= d; v.z *= d; v.w *= d;
    __nv_bfloat16 h0 = __float2bfloat16_rn(v.x);
    __nv_bfloat16 h1 = __float2bfloat16_rn(v.y);
    __nv_bfloat16 h2 = __float2bfloat16_rn(v.z);
    __nv_bfloat16 h3 = __float2bfloat16_rn(v.w);
    __nv_bfloat16 l0 = __float2bfloat16_rn(v.x - __bfloat162float(h0));
    __nv_bfloat16 l1 = __float2bfloat16_rn(v.y - __bfloat162float(h1));
    __nv_bfloat16 l2 = __float2bfloat16_rn(v.z - __bfloat162float(h2));
    __nv_bfloat16 l3 = __float2bfloat16_rn(v.w - __bfloat162float(h3));
    unsigned short* o = g_xs + (size_t)node * 128 + c4;
    ushort4 hh, ll;
    hh.x = *(unsigned short*)&h0; hh.y = *(unsigned short*)&h1;
    hh.z = *(unsigned short*)&h2; hh.w = *(unsigned short*)&h3;
    ll.x = *(unsigned short*)&l0; ll.y = *(unsigned short*)&l1;
    ll.z = *(unsigned short*)&l2; ll.w = *(unsigned short*)&l3;
    *(ushort4*)o        = hh;
    *(ushort4*)(o + 64) = ll;
}

// ---------------- fused diffusion mma + FC + instance-norm + relu ----------------
// Block: 128 thr = 4 warps; 128 rows x 128 f (hi|lo). Warp = 32 rows (2 A-tiles).
// Epilogue: lx staged in smem, FC (fp32) + instance-norm + relu; layer0 writes
// dinv-scaled bf16 split to g_xs2, layer1 writes float output.
__global__ void __launch_bounds__(128) k_mm(int layer, float* __restrict__ out_final,
                                            const float* __restrict__ W) {
    extern __shared__ char smraw[];
    unsigned short (*bs)[SP] = (unsigned short(*)[SP])smraw;   // [128][SP]: buf0 rows 0-63, buf1 64-127

    int b = blockIdx.y, n0 = blockIdx.x * 128;
    int t = threadIdx.x, wr = t >> 5, lane = t & 31;
    int g = lane >> 2, tq = lane & 3;
    int rl8 = (lane & 7) + ((lane >> 3) & 1) * 8;
    int fg = (lane >> 4) * 8;

    const unsigned short* xsrc = (layer == 0) ? g_xs : g_xs2;
    const unsigned short* xsb = xsrc + (size_t)b * NNODE * 128;
    const unsigned* padj = g_adjT + (size_t)b * 128 * NNODE + (n0 + wr * 32 + g);

    float cc[2][16][4];
    #pragma unroll
    for (int t2 = 0; t2 < 2; t2++)
        #pragma unroll
        for (int j = 0; j < 16; j++)
            #pragma unroll
            for (int q = 0; q < 4; q++) cc[t2][j][q] = 0.f;

    int srow = t >> 4, schk = t & 15;
    uint sb0 = (uint)__cvta_generic_to_shared(smraw);
    uint sb1 = sb0 + 64 * SP * 2;

    float4 pf[8];
    #pragma unroll
    for (int ps = 0; ps < 8; ps++)
        pf[ps] = *(const float4*)(xsb + (size_t)(srow + ps * 8) * 128 + schk * 8);
    #pragma unroll
    for (int ps = 0; ps < 8; ps++)
        *(float4*)&bs[srow + ps * 8][schk * 8] = pf[ps];
    #pragma unroll
    for (int ps = 0; ps < 8; ps++)
        pf[ps] = *(const float4*)(xsb + (size_t)(64 + srow + ps * 8) * 128 + schk * 8);

    uint w0[4], w1[4];
    #pragma unroll
    for (int o4 = 0; o4 < 4; o4++) {
        w0[o4] = padj[o4 * 8];
        w1[o4] = padj[(size_t)NNODE + o4 * 8];
    }

    for (int c = 0; c < 64; c++) {
        __syncthreads();
        if (c + 1 < 64) {
            unsigned short (*dst)[SP] = (unsigned short(*)[SP])(smraw + ((c + 1) & 1) * 64 * SP * 2);
            #pragma unroll
            for (int ps = 0; ps < 8; ps++)
                *(float4*)&dst[srow + ps * 8][schk * 8] = pf[ps];
            if (c + 2 < 64) {
                #pragma unroll
                for (int ps = 0; ps < 8; ps++)
                    pf[ps] = *(const float4*)(xsb + (size_t)((c + 2) * 64 + srow + ps * 8) * 128 + schk * 8);
            }
        }
        uint nw0[4] = {0, 0, 0, 0}, nw1[4] = {0, 0, 0, 0};
        if (c + 1 < 64) {
            #pragma unroll
            for (int o4 = 0; o4 < 4; o4++) {
                nw0[o4] = padj[(size_t)(2 * c + 2) * NNODE + o4 * 8];
                nw1[o4] = padj[(size_t)(2 * c + 3) * NNODE + o4 * 8];
            }
        }
        uint bb = (c & 1) ? sb1 : sb0;
        #pragma unroll
        for (int q = 0; q < 4; q++) {
            int s = ((q & 1) << 4) + 2 * tq;
            uint A0[2], A1[2], A2[2], A3[2];
            #pragma unroll
            for (int t2 = 0; t2 < 2; t2++) {
                uint wlo = (q < 2) ? w0[2 * t2] : w1[2 * t2];
                uint whi = (q < 2) ? w0[2 * t2 + 1] : w1[2 * t2 + 1];
                A0[t2] = bfpair((wlo >> s) & 3u);
                A1[t2] = bfpair((whi >> s) & 3u);
                A2[t2] = bfpair((wlo >> (s + 8)) & 3u);
                A3[t2] = bfpair((whi >> (s + 8)) & 3u);
            }
            uint baddr = bb + (uint)(((q * 16 + rl8) * SP + fg) * 2);
            #pragma unroll
            for (int p = 0; p < 8; p++) {
                uint r0, r1, r2, r3;
                asm volatile(
                    "ldmatrix.sync.aligned.m8n8.x4.trans.shared.b16 {%0,%1,%2,%3}, [%4];"
                    : "=r"(r0), "=r"(r1), "=r"(r2), "=r"(r3)
                    : "r"(baddr + (uint)(p * 32)));
                asm volatile(
                    "mma.sync.aligned.m16n8k16.row.col.f32.bf16.bf16.f32 "
                    "{%0,%1,%2,%3}, {%4,%5,%6,%7}, {%8,%9}, {%0,%1,%2,%3};"
                    : "+f"(cc[0][2 * p][0]), "+f"(cc[0][2 * p][1]), "+f"(cc[0][2 * p][2]), "+f"(cc[0][2 * p][3])
                    : "r"(A0[0]), "r"(A1[0]), "r"(A2[0]), "r"(A3[0]), "r"(r0), "r"(r1));
                asm volatile(
                    "mma.sync.aligned.m16n8k16.row.col.f32.bf16.bf16.f32 "
                    "{%0,%1,%2,%3}, {%4,%5,%6,%7}, {%8,%9}, {%0,%1,%2,%3};"
                    : "+f"(cc[0][2 * p + 1][0]), "+f"(cc[0][2 * p + 1][1]), "+f"(cc[0][2 * p + 1][2]), "+f"(cc[0][2 * p + 1][3])
                    : "r"(A0[0]), "r"(A1[0]), "r"(A2[0]), "r"(A3[0]), "r"(r2), "r"(r3));
                asm volatile(
                    "mma.sync.aligned.m16n8k16.row.col.f32.bf16.bf16.f32 "
                    "{%0,%1,%2,%3}, {%4,%5,%6,%7}, {%8,%9}, {%0,%1,%2,%3};"
                    : "+f"(cc[1][2 * p][0]), "+f"(cc[1][2 * p][1]), "+f"(cc[1][2 * p][2]), "+f"(cc[1][2 * p][3])
                    : "r"(A0[1]), "r"(A1[1]), "r"(A2[1]), "r"(A3[1]), "r"(r0), "r"(r1));
                asm volatile(
                    "mma.sync.aligned.m16n8k16.row.col.f32.bf16.bf16.f32 "
                    "{%0,%1,%2,%3}, {%4,%5,%6,%7}, {%8,%9}, {%0,%1,%2,%3};"
                    : "+f"(cc[1][2 * p + 1][0]), "+f"(cc[1][2 * p + 1][1]), "+f"(cc[1][2 * p + 1][2]), "+f"(cc[1][2 * p + 1][3])
                    : "r"(A0[1]), "r"(A1[1]), "r"(A2[1]), "r"(A3[1]), "r"(r2), "r"(r3));
            }
        }
        #pragma unroll
        for (int o4 = 0; o4 < 4; o4++) { w0[o4] = nw0[o4]; w1[o4] = nw1[o4]; }
    }
    __syncthreads();   // all mma smem reads done before repurposing smem

    // ---- epilogue: combine hi+lo, scale by dinv_n, stage lx ----
    float (*lxs)[66] = (float(*)[66])smraw;                       // [128][66]
    float (*ws)[64]  = (float(*)[64])(smraw + 128 * 66 * 4);      // [64][64]

    #pragma unroll
    for (int t2 = 0; t2 < 2; t2++) {
        int lr0 = wr * 32 + t2 * 16 + g;
        float dn0 = g_dinv[b * NNODE + n0 + lr0];
        float dn1 = g_dinv[b * NNODE + n0 + lr0 + 8];
        #pragma unroll
        for (int j = 0; j < 8; j++) {
            float2 v0 = make_float2((cc[t2][j][0] + cc[t2][j + 8][0]) * dn0,
                                    (cc[t2][j][1] + cc[t2][j + 8][1]) * dn0);
            float2 v1 = make_float2((cc[t2][j][2] + cc[t2][j + 8][2]) * dn1,
                                    (cc[t2][j][3] + cc[t2][j + 8][3]) * dn1);
            *(float2*)&lxs[lr0][j * 8 + 2 * tq]     = v0;
            *(float2*)&lxs[lr0 + 8][j * 8 + 2 * tq] = v1;
        }
    }
    {
        int c2 = t >> 1, fh = (t & 1) * 32;
        #pragma unroll
        for (int j = 0; j < 8; j++)
            *(float4*)&ws[c2][fh + j * 4] = *(const float4*)(W + c2 * 64 + fh + j * 4);
    }
    __syncthreads();

    // ---- FC: thread t owns row t (all 64 f) ----
    int lr = t;
    ull h[32];
    #pragma unroll
    for (int j = 0; j < 32; j++) h[j] = 0ULL;
    #pragma unroll 8
    for (int c = 0; c < 64; c++) {
        ull a2 = pack2(lxs[lr][c]);
        const ulonglong2* w2 = (const ulonglong2*)&ws[c][0];
        #pragma unroll
        for (int j = 0; j < 8; j++) {
            ulonglong2 u0 = w2[2 * j];
            ulonglong2 u1 = w2[2 * j + 1];
            fma2(h[4 * j],     a2, u0.x);
            fma2(h[4 * j + 1], a2, u0.y);
            fma2(h[4 * j + 2], a2, u1.x);
            fma2(h[4 * j + 3], a2, u1.y);
        }
    }
    float hv[64];
    #pragma unroll
    for (int j = 0; j < 32; j++) { F2U u; u.u = h[j]; hv[2 * j] = u.f.x; hv[2 * j + 1] = u.f.y; }

    float sum = 0.f;
    #pragma unroll
    for (int j = 0; j < 64; j++) sum += hv[j];
    float mean = sum * (1.f / 64.f);
    float vq = 0.f;
    #pragma unroll
    for (int j = 0; j < 64; j++) { float d = hv[j] - mean; vq += d * d; }
    float inv = 1.0f / sqrtf(vq * (1.f / 64.f) + EPSI);

    int gnode = b * NNODE + n0 + lr;
    if (layer == 0) {
        float d = g_dinv[gnode];
        unsigned short* o = g_xs2 + (size_t)gnode * 128;
        #pragma unroll
        for (int f4 = 0; f4 < 16; f4++) {
            ushort4 hh, ll;
            unsigned short* hp = &hh.x;
            unsigned short* lp = &ll.x;
            #pragma unroll
            for (int q = 0; q < 4; q++) {
                float y = fmaxf((hv[f4 * 4 + q] - mean) * inv, 0.f) * d;
                __nv_bfloat16 hb = __float2bfloat16_rn(y);
                __nv_bfloat16 lb = __float2bfloat16_rn(y - __bfloat162float(hb));
                hp[q] = *(unsigned short*)&hb;
                lp[q] = *(unsigned short*)&lb;
            }
            *(ushort4*)(o + f4 * 4)      = hh;
            *(ushort4*)(o + 64 + f4 * 4) = ll;
        }
    } else {
        float* op = out_final + (size_t)gnode * 64;
        #pragma unroll
        for (int f4 = 0; f4 < 16; f4++) {
            float4 ov;
            ov.x = fmaxf((hv[f4 * 4 + 0] - mean) * inv, 0.f);
            ov.y = fmaxf((hv[f4 * 4 + 1] - mean) * inv, 0.f);
            ov.z = fmaxf((hv[f4 * 4 + 2] - mean) * inv, 0.f);
            ov.w = fmaxf((hv[f4 * 4 + 3] - mean) * inv, 0.f);
            *(float4*)(op + f4 * 4) = ov;
        }
    }
}

// ---------------- launch ----------------
#define SMEM_MM 50176   // max(2*64*SP*2 = 34816, 128*66*4 + 64*64*4 = 50176)

extern "C" void kernel_launch(void* const* d_in, const int* in_sizes, int n_in,
                              void* d_out, int out_size) {
    const float* x  = (const float*)d_in[0];
    const float* W0 = (const float*)d_in[1];
    const float* W1 = (const float*)d_in[2];
    float* out = (float*)d_out;

    cudaFuncSetAttribute(k_mm, cudaFuncAttributeMaxDynamicSharedMemorySize, SMEM_MM);

    k_transpose<<<dim3(128, 2, 4), dim3(32, 8)>>>(x);
    k_norm<<<64, 256>>>();
    k_gram<<<dim3(272, 1, 4), 256>>>(x);
    k_deg<<<128, 128>>>();
    k_split<<<1024, 256>>>();
    k_mm<<<dim3(32, 4), 128, SMEM_MM>>>(0, nullptr, W0);
    k_mm<<<dim3(32, 4), 128, SMEM_MM>>>(1, out, W1);
}

// round 7
// speedup vs baseline: 1.1638x; 1.1638x over previous
#include <cuda_runtime.h>
#include <cuda_bf16.h>
#include <math.h>

#define THR 0.005f
#define EPSI 1e-5f
#define NBATCH 4
#define NNODE 4096
#define NCH 64
#define SP 136   // padded bf16 row stride for B smem tile

typedef unsigned long long ull;
typedef unsigned int uint;

// ---------------- device scratch ----------------
__device__ __align__(16) float g_xt[NBATCH * NNODE * NCH];     // x transposed [b][n][c]
__device__ __align__(16) float g_snorm[NBATCH * NNODE];
__device__ __align__(16) float g_dinv[NBATCH * NNODE];
__device__ __align__(16) unsigned g_adjT[NBATCH * 128 * NNODE];       // bits [b][word_m][n]
__device__ __align__(16) unsigned short g_xs [NBATCH * NNODE * 128];  // bf16 split layer0 in
__device__ __align__(16) unsigned short g_xs2[NBATCH * NNODE * 128];  // bf16 split layer1 in

// ---------------- helpers ----------------
__device__ __forceinline__ void fma2(ull& d, ull a, ull b) {
    asm("fma.rn.f32x2 %0, %1, %2, %0;" : "+l"(d) : "l"(a), "l"(b));
}
__device__ __forceinline__ ull pack2(float x) {
    ull r; asm("mov.b64 %0, {%1, %1};" : "=l"(r) : "f"(x)); return r;
}
union F2U { ull u; float2 f; };

__device__ __forceinline__ uint bfpair(uint u) {
    return ((u & 1u) ? 0x3F80u : 0u) | ((u & 2u) ? 0x3F800000u : 0u);
}

// ---------------- transpose & norms ----------------
__global__ void k_transpose(const float* __restrict__ x) {
    __shared__ float t[32][33];
    int b = blockIdx.z, c0 = blockIdx.y * 32, n0 = blockIdx.x * 32;
    int tx = threadIdx.x, ty = threadIdx.y;
    const float* xp = x + ((b * 64 + c0) * NNODE) + n0;
    #pragma unroll
    for (int i = ty; i < 32; i += 8) t[i][tx] = xp[i * NNODE + tx];
    __syncthreads();
    float* op = g_xt + ((b * NNODE + n0) * 64) + c0;
    #pragma unroll
    for (int i = ty; i < 32; i += 8) op[i * 64 + tx] = t[tx][i];
}

__global__ void k_norm() {
    int i = blockIdx.x * 256 + threadIdx.x;
    if (i >= NBATCH * NNODE) return;
    const float4* p = (const float4*)(g_xt + (size_t)i * 64);
    float s = 0.f;
    #pragma unroll
    for (int j = 0; j < 16; j++) {
        float4 v = p[j];
        s += v.x * v.x + v.y * v.y + v.z * v.z + v.w * v.w;
    }
    g_snorm[i] = sqrtf(s);
}

// ---------------- Gram + threshold -> adjacency bits ----------------
// Block 128n x 128m tile (triangular pairs), 8 warps. Warp: 32n x 64m.
// Thread tile 8n x 8m. A pre-duplicated in SMEM as {a,a} u64 pairs -> inner
// loop has NO pack movs: 6 LDS + 32 fma2 per warp-k. K in 4 chunks of 16.
__global__ void __launch_bounds__(256, 2) k_gram(const float* __restrict__ x) {
    __shared__ __align__(16) ull   As2[16][128];   // 16KB duplicated A
    __shared__ __align__(16) float Bs[16][128];    // 8KB
    __shared__ float sns[128], pms[128];

    int b = blockIdx.z;
    int xid = blockIdx.x;
    int bj = (int)((sqrtf(8.f * xid + 1.f) - 1.f) * 0.5f);
    while ((bj + 1) * (bj + 2) / 2 <= xid) bj++;
    while (bj * (bj + 1) / 2 > xid) bj--;
    int bi = xid - bj * (bj + 1) / 2;
    int n0 = bi * 128, m0 = bj * 128;

    int t = threadIdx.x;
    if (t < 128) sns[t] = g_snorm[b * NNODE + n0 + t];
    else         pms[t - 128] = THR * g_snorm[b * NNODE + m0 + (t - 128)];

    int warp = t >> 5, lane = t & 31;
    int r = lane >> 3, c3 = lane & 7;
    int warpn = (warp >> 1) * 32;
    int nb = warpn + r * 8;
    int mwarp = (warp & 1) * 64;
    int mb = mwarp + c3 * 4;

    ull acc[8][4];
    #pragma unroll
    for (int i = 0; i < 8; i++)
        #pragma unroll
        for (int p = 0; p < 4; p++) acc[i][p] = 0ULL;

    const float* xa = x + (size_t)(b * 64) * NNODE;

    // staging map: 2 float4 for A, 2 for B per thread per 16-k chunk
    int row_s = (t + 0) >> 5;        // reused pattern below with i*256
    (void)row_s;

    float4 pA[2], pB[2];
    #pragma unroll
    for (int i = 0; i < 2; i++) {
        int f4 = t + i * 256;
        int row = f4 >> 5, c4 = f4 & 31;
        pA[i] = *(const float4*)(xa + (size_t)row * NNODE + n0 + c4 * 4);
        pB[i] = *(const float4*)(xa + (size_t)row * NNODE + m0 + c4 * 4);
    }

    for (int kc = 0; kc < 4; kc++) {
        __syncthreads();
        #pragma unroll
        for (int i = 0; i < 2; i++) {
            int f4 = t + i * 256;
            int row = f4 >> 5, c4 = f4 & 31;
            float4 v = pA[i];
            ull* ap = &As2[row][c4 * 4];
            ap[0] = pack2(v.x); ap[1] = pack2(v.y);
            ap[2] = pack2(v.z); ap[3] = pack2(v.w);
            *(float4*)&Bs[row][c4 * 4] = pB[i];
        }
        __syncthreads();
        if (kc < 3) {
            int kb = (kc + 1) * 16;
            #pragma unroll
            for (int i = 0; i < 2; i++) {
                int f4 = t + i * 256;
                int row = f4 >> 5, c4 = f4 & 31;
                pA[i] = *(const float4*)(xa + (size_t)(kb + row) * NNODE + n0 + c4 * 4);
                pB[i] = *(const float4*)(xa + (size_t)(kb + row) * NNODE + m0 + c4 * 4);
            }
        }
        #pragma unroll
        for (int k = 0; k < 16; k++) {
            const ulonglong2* ap = (const ulonglong2*)&As2[k][nb];
            ulonglong2 b0 = *(const ulonglong2*)&Bs[k][mb];
            ulonglong2 b1 = *(const ulonglong2*)&Bs[k][mb + 32];
            #pragma unroll
            for (int h = 0; h < 4; h++) {
                ulonglong2 a2 = ap[h];
                fma2(acc[2 * h][0], a2.x, b0.x); fma2(acc[2 * h][1], a2.x, b0.y);
                fma2(acc[2 * h][2], a2.x, b1.x); fma2(acc[2 * h][3], a2.x, b1.y);
                fma2(acc[2 * h + 1][0], a2.y, b0.x); fma2(acc[2 * h + 1][1], a2.y, b0.y);
                fma2(acc[2 * h + 1][2], a2.y, b1.x); fma2(acc[2 * h + 1][3], a2.y, b1.y);
            }
        }
    }

    // ---- threshold + both-orientation bit packing (identical to R4) ----
    float pmv[8];
    #pragma unroll
    for (int j = 0; j < 4; j++) {
        pmv[j]     = pms[mwarp + c3 * 4 + j];
        pmv[4 + j] = pms[mwarp + 32 + c3 * 4 + j];
    }
    unsigned bytesT[8];
    #pragma unroll
    for (int j = 0; j < 8; j++) bytesT[j] = 0u;

    int bw = (m0 + mwarp) >> 5;
    int nw = (n0 + warpn) >> 5;

    #pragma unroll
    for (int i = 0; i < 8; i++) {
        float sni = sns[nb + i];
        F2U q0, q1, q2, q3;
        q0.u = acc[i][0]; q1.u = acc[i][1]; q2.u = acc[i][2]; q3.u = acc[i][3];
        unsigned c0 = q0.f.x > sni * pmv[0];
        unsigned c1 = q0.f.y > sni * pmv[1];
        unsigned c2 = q1.f.x > sni * pmv[2];
        unsigned c3b = q1.f.y > sni * pmv[3];
        unsigned c4 = q2.f.x > sni * pmv[4];
        unsigned c5 = q2.f.y > sni * pmv[5];
        unsigned c6 = q3.f.x > sni * pmv[6];
        unsigned c7 = q3.f.y > sni * pmv[7];
        unsigned v0 = (c0 | (c1 << 1) | (c2 << 2) | (c3b << 3)) << (c3 * 4);
        unsigned v1 = (c4 | (c5 << 1) | (c6 << 2) | (c7 << 3)) << (c3 * 4);
        bytesT[0] |= c0 << i;  bytesT[1] |= c1 << i;
        bytesT[2] |= c2 << i;  bytesT[3] |= c3b << i;
        bytesT[4] |= c4 << i;  bytesT[5] |= c5 << i;
        bytesT[6] |= c6 << i;  bytesT[7] |= c7 << i;
        #pragma unroll
        for (int s = 1; s <= 4; s <<= 1) {
            v0 |= __shfl_xor_sync(0xffffffffu, v0, s);
            v1 |= __shfl_xor_sync(0xffffffffu, v1, s);
        }
        if (c3 == 0) {
            int gn = n0 + nb + i;
            g_adjT[((size_t)b * 128 + bw)     * NNODE + gn] = v0;
            g_adjT[((size_t)b * 128 + bw + 1) * NNODE + gn] = v1;
        }
    }
    #pragma unroll
    for (int jj = 0; jj < 8; jj++) {
        unsigned v = bytesT[jj] << (r * 8);
        v |= __shfl_xor_sync(0xffffffffu, v, 8);
        v |= __shfl_xor_sync(0xffffffffu, v, 16);
        if (r == 0) {
            int mg = m0 + mwarp + ((jj < 4) ? (c3 * 4 + jj) : (32 + c3 * 4 + jj - 4));
            g_adjT[((size_t)b * 128 + nw) * NNODE + mg] = v;
        }
    }
}

// ---------------- fused degree + dinv + layer0 split ----------------
// Block 128 thr = 4 warps, 32 nodes per block, each warp popcs 32 of 128 words.
__global__ void __launch_bounds__(128) k_degsplit() {
    __shared__ int sc[4][32];
    __shared__ float sdv[32];

    int i0 = blockIdx.x * 32;                 // 512 blocks
    int t = threadIdx.x, q = t >> 5, lane = t & 31;
    int gi = i0 + lane;
    int b = gi >> 12, nl = gi & 4095;
    const unsigned* base = g_adjT + (size_t)b * 128 * NNODE + nl;
    int c = 0;
    #pragma unroll 8
    for (int j = 0; j < 32; j++)
        c += __popc(base[(size_t)(q * 32 + j) * NNODE]);
    sc[q][lane] = c;
    __syncthreads();
    if (t < 32) {
        int tot = sc[0][t] + sc[1][t] + sc[2][t] + sc[3][t];
        float d = 1.0f / sqrtf((float)tot);
        g_dinv[i0 + t] = d;
        sdv[t] = d;
    }
    __syncthreads();

    // split: thread -> (node = t>>2, quad = t&3), 16 floats each
    int node = i0 + (t >> 2);
    float d = sdv[t >> 2];
    const float4* src = (const float4*)(g_xt + (size_t)node * 64 + (t & 3) * 16);
    unsigned short* o = g_xs + (size_t)node * 128 + (t & 3) * 16;
    #pragma unroll
    for (int j = 0; j < 4; j++) {
        float4 v = src[j];
        v.x *= d; v.y *= d; v.z *= d; v.w *= d;
        __nv_bfloat16 h0 = __float2bfloat16_rn(v.x);
        __nv_bfloat16 h1 = __float2bfloat16_rn(v.y);
        __nv_bfloat16 h2 = __float2bfloat16_rn(v.z);
        __nv_bfloat16 h3 = __float2bfloat16_rn(v.w);
        __nv_bfloat16 l0 = __float2bfloat16_rn(v.x - __bfloat162float(h0));
        __nv_bfloat16 l1 = __float2bfloat16_rn(v.y - __bfloat162float(h1));
        __nv_bfloat16 l2 = __float2bfloat16_rn(v.z - __bfloat162float(h2));
        __nv_bfloat16 l3 = __float2bfloat16_rn(v.w - __bfloat162float(h3));
        ushort4 hh, ll;
        hh.x = *(unsigned short*)&h0; hh.y = *(unsigned short*)&h1;
        hh.z = *(unsigned short*)&h2; hh.w = *(unsigned short*)&h3;
        ll.x = *(unsigned short*)&l0; ll.y = *(unsigned short*)&l1;
        ll.z = *(unsigned short*)&l2; ll.w = *(unsigned short*)&l3;
        *(ushort4*)(o + j * 4)      = hh;
        *(ushort4*)(o + 64 + j * 4) = ll;
    }
}

// ---------------- fused diffusion mma + FC + instance-norm + relu ----------------
// Mainloop IDENTICAL to the 282.8us version: 4 warps, 64 rows x 128 f (hi|lo),
// warp = 16 rows, bits->A frags in regs, ldmatrix B, double-buffered smem.
// Epilogue: lx staged to smem, FC fp32x2 (2 thr/row, 32 f each), instance-norm,
// relu; layer0 emits dinv-scaled bf16 split to g_xs2, layer1 writes output.
__global__ void __launch_bounds__(128) k_mm(int layer, float* __restrict__ out_final,
                                            const float* __restrict__ W) {
    __shared__ union {
        unsigned short bs[2][64][SP];                    // 34816 B (mainloop)
        struct { float lxs[64][68]; float ws[64][64]; } e;  // 33792 B (epilogue)
    } SM;

    int b = blockIdx.y, n0 = blockIdx.x * 64;
    int t = threadIdx.x, wr = t >> 5, lane = t & 31;
    int g = lane >> 2, tq = lane & 3;
    int rl8 = (lane & 7) + ((lane >> 3) & 1) * 8;
    int fg = (lane >> 4) * 8;

    const unsigned short* xsrc = (layer == 0) ? g_xs : g_xs2;
    const unsigned short* xsb = xsrc + (size_t)b * NNODE * 128;
    const unsigned* pa = g_adjT + (size_t)b * 128 * NNODE + (n0 + wr * 16 + g);
    const unsigned* pa8 = pa + 8;

    float cc[16][4];
    #pragma unroll
    for (int j = 0; j < 16; j++)
        #pragma unroll
        for (int q = 0; q < 4; q++) cc[j][q] = 0.f;

    int srow = t >> 4, schk = t & 15;
    uint sb0 = (uint)__cvta_generic_to_shared(&SM.bs[0][0][0]);
    uint sb1 = (uint)__cvta_generic_to_shared(&SM.bs[1][0][0]);

    float4 pf[8];
    #pragma unroll
    for (int ps = 0; ps < 8; ps++)
        pf[ps] = *(const float4*)(xsb + (size_t)(srow + ps * 8) * 128 + schk * 8);
    #pragma unroll
    for (int ps = 0; ps < 8; ps++)
        *(float4*)&SM.bs[0][srow + ps * 8][schk * 8] = pf[ps];
    #pragma unroll
    for (int ps = 0; ps < 8; ps++)
        pf[ps] = *(const float4*)(xsb + (size_t)(64 + srow + ps * 8) * 128 + schk * 8);
    unsigned w0a = pa[0], w1a = pa[(size_t)4096];
    unsigned w0b = pa8[0], w1b = pa8[(size_t)4096];

    for (int c = 0; c < 64; c++) {
        __syncthreads();
        if (c + 1 < 64) {
            #pragma unroll
            for (int ps = 0; ps < 8; ps++)
                *(float4*)&SM.bs[(c + 1) & 1][srow + ps * 8][schk * 8] = pf[ps];
            if (c + 2 < 64) {
                #pragma unroll
                for (int ps = 0; ps < 8; ps++)
                    pf[ps] = *(const float4*)(xsb + (size_t)((c + 2) * 64 + srow + ps * 8) * 128 + schk * 8);
            }
        }
        unsigned nw0a = 0, nw1a = 0, nw0b = 0, nw1b = 0;
        if (c + 1 < 64) {
            nw0a = pa[(size_t)(2 * c + 2) * 4096];
            nw1a = pa[(size_t)(2 * c + 3) * 4096];
            nw0b = pa8[(size_t)(2 * c + 2) * 4096];
            nw1b = pa8[(size_t)(2 * c + 3) * 4096];
        }
        uint bb = (c & 1) ? sb1 : sb0;
        #pragma unroll
        for (int q = 0; q < 4; q++) {
            unsigned wA = (q < 2) ? w0a : w1a;
            unsigned wB = (q < 2) ? w0b : w1b;
            int s = ((q & 1) << 4) + 2 * tq;
            uint a0 = bfpair((wA >> s) & 3u);
            uint a2 = bfpair((wA >> (s + 8)) & 3u);
            uint a1 = bfpair((wB >> s) & 3u);
            uint a3 = bfpair((wB >> (s + 8)) & 3u);
            uint baddr = bb + (uint)(((q * 16 + rl8) * SP + fg) * 2);
            #pragma unroll
            for (int p = 0; p < 8; p++) {
                uint r0, r1, r2, r3;
                asm volatile(
                    "ldmatrix.sync.aligned.m8n8.x4.trans.shared.b16 {%0,%1,%2,%3}, [%4];"
                    : "=r"(r0), "=r"(r1), "=r"(r2), "=r"(r3)
                    : "r"(baddr + (uint)(p * 32)));
                asm volatile(
                    "mma.sync.aligned.m16n8k16.row.col.f32.bf16.bf16.f32 "
                    "{%0,%1,%2,%3}, {%4,%5,%6,%7}, {%8,%9}, {%0,%1,%2,%3};"
                    : "+f"(cc[2 * p][0]), "+f"(cc[2 * p][1]), "+f"(cc[2 * p][2]), "+f"(cc[2 * p][3])
                    : "r"(a0), "r"(a1), "r"(a2), "r"(a3), "r"(r0), "r"(r1));
                asm volatile(
                    "mma.sync.aligned.m16n8k16.row.col.f32.bf16.bf16.f32 "
                    "{%0,%1,%2,%3}, {%4,%5,%6,%7}, {%8,%9}, {%0,%1,%2,%3};"
                    : "+f"(cc[2 * p + 1][0]), "+f"(cc[2 * p + 1][1]), "+f"(cc[2 * p + 1][2]), "+f"(cc[2 * p + 1][3])
                    : "r"(a0), "r"(a1), "r"(a2), "r"(a3), "r"(r2), "r"(r3));
            }
        }
        w0a = nw0a; w1a = nw1a; w0b = nw0b; w1b = nw1b;
    }
    __syncthreads();   // all mma smem reads done before repurposing smem

    // ---- epilogue: combine hi+lo, scale by dinv_n, stage lx to smem ----
    {
        int lr0 = wr * 16 + g;
        float dn0 = g_dinv[b * NNODE + n0 + lr0];
        float dn1 = g_dinv[b * NNODE + n0 + lr0 + 8];
        #pragma unroll
        for (int j = 0; j < 8; j++) {
            int col = j * 8 + 2 * tq;
            float2 u0 = make_float2((cc[j][0] + cc[j + 8][0]) * dn0,
                                    (cc[j][1] + cc[j + 8][1]) * dn0);
            float2 u1 = make_float2((cc[j][2] + cc[j + 8][2]) * dn1,
                                    (cc[j][3] + cc[j + 8][3]) * dn1);
            *(float2*)&SM.e.lxs[lr0][col]     = u0;
            *(float2*)&SM.e.lxs[lr0 + 8][col] = u1;
        }
    }
    // stage W: thread t loads 8 float4 (row = t>>1, half = t&1)
    {
        int c2 = t >> 1, fh = (t & 1) * 32;
        #pragma unroll
        for (int j = 0; j < 8; j++)
            *(float4*)&SM.e.ws[c2][fh + j * 4] = *(const float4*)(W + c2 * 64 + fh + j * 4);
    }
    __syncthreads();

    // ---- FC: 2 threads per row, 32 f each ----
    int row = t >> 1, fh = (t & 1) * 32;
    ull h[16];
    #pragma unroll
    for (int j = 0; j < 16; j++) h[j] = 0ULL;
    #pragma unroll 8
    for (int c = 0; c < 64; c++) {
        ull a2 = pack2(SM.e.lxs[row][c]);
        const ulonglong2* w2 = (const ulonglong2*)&SM.e.ws[c][fh];
        #pragma unroll
        for (int j = 0; j < 4; j++) {
            ulonglong2 u0 = w2[2 * j];
            ulonglong2 u1 = w2[2 * j + 1];
            fma2(h[4 * j],     a2, u0.x);
            fma2(h[4 * j + 1], a2, u0.y);
            fma2(h[4 * j + 2], a2, u1.x);
            fma2(h[4 * j + 3], a2, u1.y);
        }
    }
    float hv[32];
    #pragma unroll
    for (int j = 0; j < 16; j++) { F2U u; u.u = h[j]; hv[2 * j] = u.f.x; hv[2 * j + 1] = u.f.y; }

    float sum = 0.f;
    #pragma unroll
    for (int j = 0; j < 32; j++) sum += hv[j];
    sum += __shfl_xor_sync(0xffffffffu, sum, 1);
    float mean = sum * (1.f / 64.f);
    float vq = 0.f;
    #pragma unroll
    for (int j = 0; j < 32; j++) { float d = hv[j] - mean; vq += d * d; }
    vq += __shfl_xor_sync(0xffffffffu, vq, 1);
    float inv = 1.0f / sqrtf(vq * (1.f / 64.f) + EPSI);

    int gnode = b * NNODE + n0 + row;
    if (layer == 0) {
        float d = g_dinv[gnode];
        unsigned short* o = g_xs2 + (size_t)gnode * 128 + fh;
        #pragma unroll
        for (int f4 = 0; f4 < 8; f4++) {
            ushort4 hh, ll;
            unsigned short* hp = &hh.x;
            unsigned short* lp = &ll.x;
            #pragma unroll
            for (int q = 0; q < 4; q++) {
                float y = fmaxf((hv[f4 * 4 + q] - mean) * inv, 0.f) * d;
                __nv_bfloat16 hb = __float2bfloat16_rn(y);
                __nv_bfloat16 lb = __float2bfloat16_rn(y - __bfloat162float(hb));
                hp[q] = *(unsigned short*)&hb;
                lp[q] = *(unsigned short*)&lb;
            }
            *(ushort4*)(o + f4 * 4)      = hh;
            *(ushort4*)(o + 64 + f4 * 4) = ll;
        }
    } else {
        float* op = out_final + (size_t)gnode * 64 + fh;
        #pragma unroll
        for (int f4 = 0; f4 < 8; f4++) {
            float4 ov;
            ov.x = fmaxf((hv[f4 * 4 + 0] - mean) * inv, 0.f);
            ov.y = fmaxf((hv[f4 * 4 + 1] - mean) * inv, 0.f);
            ov.z = fmaxf((hv[f4 * 4 + 2] - mean) * inv, 0.f);
            ov.w = fmaxf((hv[f4 * 4 + 3] - mean) * inv, 0.f);
            *(float4*)(op + f4 * 4) = ov;
        }
    }
}

// ---------------- launch ----------------
extern "C" void kernel_launch(void* const* d_in, const int* in_sizes, int n_in,
                              void* d_out, int out_size) {
    const float* x  = (const float*)d_in[0];
    const float* W0 = (const float*)d_in[1];
    const float* W1 = (const float*)d_in[2];
    float* out = (float*)d_out;

    k_transpose<<<dim3(128, 2, 4), dim3(32, 8)>>>(x);
    k_norm<<<64, 256>>>();
    k_gram<<<dim3(528, 1, 4), 256>>>(x);
    k_degsplit<<<512, 128>>>();
    k_mm<<<dim3(64, 4), 128>>>(0, nullptr, W0);
    k_mm<<<dim3(64, 4), 128>>>(1, out, W1);
}

// round 8
// speedup vs baseline: 1.2282x; 1.0553x over previous
#include <cuda_runtime.h>
#include <cuda_bf16.h>
#include <math.h>

#define THR 0.005f
#define EPSI 1e-5f
#define NBATCH 4
#define NNODE 4096
#define NCH 64
#define SP 136   // padded bf16 row stride for k_mm B smem tile

typedef unsigned long long ull;
typedef unsigned int uint;

// ---------------- device scratch ----------------
__device__ __align__(16) float g_xt[NBATCH * NNODE * NCH];     // x transposed [b][n][c]
__device__ __align__(16) float g_snorm[NBATCH * NNODE];
__device__ __align__(16) float g_dinv[NBATCH * NNODE];
__device__ __align__(16) unsigned g_adjT[NBATCH * 128 * NNODE];       // bits [b][word_m][n]
__device__ __align__(16) unsigned short g_xs [NBATCH * NNODE * 128];  // bf16 split layer0 in
__device__ __align__(16) unsigned short g_xs2[NBATCH * NNODE * 128];  // bf16 split layer1 in
// tf32 split fragments for gram (A-side 16-row frag layout, B-side 8-row frag layout)
__device__ __align__(16) unsigned g_ta[NBATCH * 256 * 2048];   // [b][g16][kc][part][lane][4]
__device__ __align__(16) unsigned g_tb[NBATCH * 512 * 1024];   // [b][mt8][kc][lane][4]=(h0,h1,l0,l1)

// ---------------- helpers ----------------
__device__ __forceinline__ void fma2(ull& d, ull a, ull b) {
    asm("fma.rn.f32x2 %0, %1, %2, %0;" : "+l"(d) : "l"(a), "l"(b));
}
__device__ __forceinline__ ull pack2(float x) {
    ull r; asm("mov.b64 %0, {%1, %1};" : "=l"(r) : "f"(x)); return r;
}
union F2U { ull u; float2 f; };

__device__ __forceinline__ uint bfpair(uint u) {
    return ((u & 1u) ? 0x3F80u : 0u) | ((u & 2u) ? 0x3F800000u : 0u);
}
__device__ __forceinline__ uint tf32r(float x) {
    uint r; asm("cvt.rna.tf32.f32 %0, %1;" : "=r"(r) : "f"(x)); return r;
}

#define MMA_T32(c, a, b0_, b1_) \
    asm volatile("mma.sync.aligned.m16n8k8.row.col.f32.tf32.tf32.f32 " \
        "{%0,%1,%2,%3},{%4,%5,%6,%7},{%8,%9},{%0,%1,%2,%3};" \
        : "+f"((c)[0]), "+f"((c)[1]), "+f"((c)[2]), "+f"((c)[3]) \
        : "r"((a).x), "r"((a).y), "r"((a).z), "r"((a).w), "r"(b0_), "r"(b1_))

// ---------------- transpose ----------------
__global__ void k_transpose(const float* __restrict__ x) {
    __shared__ float t[32][33];
    int b = blockIdx.z, c0 = blockIdx.y * 32, n0 = blockIdx.x * 32;
    int tx = threadIdx.x, ty = threadIdx.y;
    const float* xp = x + ((b * 64 + c0) * NNODE) + n0;
    #pragma unroll
    for (int i = ty; i < 32; i += 8) t[i][tx] = xp[i * NNODE + tx];
    __syncthreads();
    float* op = g_xt + ((b * NNODE + n0) * 64) + c0;
    #pragma unroll
    for (int i = ty; i < 32; i += 8) op[i * 64 + tx] = t[tx][i];
}

// ---------------- prep: tf32 split fragments + node norms ----------------
// Block: 128 nodes x all 64 channels, 256 threads.
__global__ void __launch_bounds__(256) k_prep(const float* __restrict__ x) {
    __shared__ float xs[64][132];
    int b = blockIdx.y, n0 = blockIdx.x * 128;
    int t = threadIdx.x;

    for (int i = t; i < 2048; i += 256) {
        int c = i >> 5, c4 = i & 31;
        float4 v = *(const float4*)(x + ((size_t)(b * 64 + c)) * NNODE + n0 + c4 * 4);
        xs[c][c4 * 4 + 0] = v.x; xs[c][c4 * 4 + 1] = v.y;
        xs[c][c4 * 4 + 2] = v.z; xs[c][c4 * 4 + 3] = v.w;
    }
    __syncthreads();

    if (t < 128) {
        float s = 0.f;
        #pragma unroll
        for (int c = 0; c < 64; c++) { float v = xs[c][t]; s += v * v; }
        g_snorm[b * NNODE + n0 + t] = sqrtf(s);
    }

    // A-side fragments: [g16][kc][part][lane][slot]
    unsigned* outA = g_ta + ((size_t)b * 256 + (n0 >> 4)) * 2048;
    #pragma unroll
    for (int i = 0; i < 16; i++) {
        int f = t + i * 256;
        int lane = f & 31, part = (f >> 5) & 1, kc = (f >> 6) & 7, gl = f >> 9;
        uint4 o;
        unsigned* op = &o.x;
        #pragma unroll
        for (int s = 0; s < 4; s++) {
            int nl = gl * 16 + (lane >> 2) + (s & 1) * 8;
            int k  = kc * 8 + (lane & 3) + ((s >> 1) & 1) * 4;
            float xv = xs[k][nl];
            unsigned hi = tf32r(xv);
            op[s] = part ? tf32r(xv - __uint_as_float(hi)) : hi;
        }
        *(uint4*)(outA + (size_t)f * 4) = o;
    }
    // B-side fragments: [mt8][kc][lane][4] = (h0,h1,l0,l1)
    unsigned* outB = g_tb + ((size_t)b * 512 + (n0 >> 3)) * 1024;
    #pragma unroll
    for (int i = 0; i < 16; i++) {
        int f = t + i * 256;
        int lane = f & 31, kc = (f >> 5) & 7, mtl = f >> 8;
        int m = mtl * 8 + (lane >> 2);
        int k0 = kc * 8 + (lane & 3);
        float x0 = xs[k0][m], x1 = xs[k0 + 4][m];
        unsigned h0 = tf32r(x0), h1 = tf32r(x1);
        uint4 o;
        o.x = h0; o.y = h1;
        o.z = tf32r(x0 - __uint_as_float(h0));
        o.w = tf32r(x1 - __uint_as_float(h1));
        *(uint4*)(outB + (size_t)f * 4) = o;
    }
}

// ---------------- Gram via tf32 mma (3-pass split) + threshold -> bits ----------------
// Block 256 thr = 8 warps; tile 128n x 128m (triangular pairs, both orientations
// written; transposed write skipped on diagonal). Warp = 32n x 64m.
// Full K=64 staged once via cp.async (128KB), then 8 kc-chunks of pure mma.
__global__ void __launch_bounds__(256) k_gram() {
    extern __shared__ float smf[];
    int b = blockIdx.y;
    int xid = blockIdx.x;
    int bj = (int)((sqrtf(8.f * xid + 1.f) - 1.f) * 0.5f);
    while ((bj + 1) * (bj + 2) / 2 <= xid) bj++;
    while (bj * (bj + 1) / 2 > xid) bj--;
    int bi = xid - bj * (bj + 1) / 2;
    int n0 = bi * 128, m0 = bj * 128;

    int t = threadIdx.x, warp = t >> 5, lane = t & 31;
    int wn = warp >> 1, wm = warp & 1;

    float* sns = smf + 32768;
    float* sms = smf + 32896;

    // stage tf32 fragments (64KB A + 64KB B) via cp.async
    {
        uint sa = (uint)__cvta_generic_to_shared(smf);
        const char* gA = (const char*)(g_ta + ((size_t)b * 256 + (n0 >> 4)) * 2048);
        const char* gB = (const char*)(g_tb + ((size_t)b * 512 + (m0 >> 3)) * 1024);
        #pragma unroll
        for (int i = 0; i < 16; i++) {
            uint off = (uint)(t + i * 256) * 16;
            asm volatile("cp.async.cg.shared.global [%0], [%1], 16;"
                         :: "r"(sa + off), "l"(gA + off));
            asm volatile("cp.async.cg.shared.global [%0], [%1], 16;"
                         :: "r"(sa + 65536 + off), "l"(gB + off));
        }
        if (t < 128) sns[t] = g_snorm[b * NNODE + n0 + t];
        else         sms[t - 128] = g_snorm[b * NNODE + m0 + (t - 128)];
        asm volatile("cp.async.commit_group;");
        asm volatile("cp.async.wait_group 0;" ::: "memory");
    }
    __syncthreads();

    float cc[2][8][4];
    #pragma unroll
    for (int t2 = 0; t2 < 2; t2++)
        #pragma unroll
        for (int j = 0; j < 8; j++)
            #pragma unroll
            for (int q = 0; q < 4; q++) cc[t2][j][q] = 0.f;

    const uint4* A4 = (const uint4*)smf;
    const uint4* B4 = A4 + 4096;

    #pragma unroll
    for (int kc = 0; kc < 8; kc++) {
        uint4 ah[2], al[2];
        #pragma unroll
        for (int t2 = 0; t2 < 2; t2++) {
            int g = wn * 2 + t2;
            int ofs = ((g * 8 + kc) * 2) * 32 + lane;
            ah[t2] = A4[ofs];
            al[t2] = A4[ofs + 32];
        }
        #pragma unroll
        for (int j = 0; j < 8; j++) {
            int mt = wm * 8 + j;
            uint4 bv = B4[(mt * 8 + kc) * 32 + lane];
            #pragma unroll
            for (int t2 = 0; t2 < 2; t2++) {
                MMA_T32(cc[t2][j], ah[t2], bv.x, bv.y);   // hh
                MMA_T32(cc[t2][j], ah[t2], bv.z, bv.w);   // h*l
                MMA_T32(cc[t2][j], al[t2], bv.x, bv.y);   // l*h
            }
        }
    }

    // ---- threshold + bit packing ----
    int q = lane & 3, gid = lane >> 2;
    uint cb[2][2];
    #pragma unroll
    for (int t2 = 0; t2 < 2; t2++) {
        #pragma unroll
        for (int rh = 0; rh < 2; rh++) {
            int rl = wn * 32 + t2 * 16 + rh * 8 + gid;
            float sn = sns[rl];
            uint c = 0;
            #pragma unroll
            for (int j = 0; j < 8; j++) {
                int ml = wm * 64 + j * 8 + 2 * q;
                uint c0 = (cc[t2][j][rh * 2]     > THR * (sn * sms[ml]))     ? 1u : 0u;
                uint c1 = (cc[t2][j][rh * 2 + 1] > THR * (sn * sms[ml + 1])) ? 1u : 0u;
                c |= (c0 << (2 * j)) | (c1 << (2 * j + 1));
            }
            cb[t2][rh] = c;
            // normal orientation: words over m for this row
            uint w0 = 0, w1 = 0;
            #pragma unroll
            for (int j = 0; j < 4; j++) {
                w0 |= ((c >> (2 * j)) & 1u)     << (j * 8 + 2 * q);
                w0 |= ((c >> (2 * j + 1)) & 1u) << (j * 8 + 2 * q + 1);
                w1 |= ((c >> (2 * j + 8)) & 1u) << (j * 8 + 2 * q);
                w1 |= ((c >> (2 * j + 9)) & 1u) << (j * 8 + 2 * q + 1);
            }
            w0 |= __shfl_xor_sync(0xffffffffu, w0, 1);
            w0 |= __shfl_xor_sync(0xffffffffu, w0, 2);
            w1 |= __shfl_xor_sync(0xffffffffu, w1, 1);
            w1 |= __shfl_xor_sync(0xffffffffu, w1, 2);
            if (q == 0) {
                int gn = n0 + rl;
                g_adjT[((size_t)b * 128 + (m0 >> 5) + wm * 2)     * NNODE + gn] = w0;
                g_adjT[((size_t)b * 128 + (m0 >> 5) + wm * 2 + 1) * NNODE + gn] = w1;
            }
        }
    }
    // transposed orientation (skip on diagonal tiles -> no duplicate writes)
    if (bi != bj) {
        #pragma unroll
        for (int idx = 0; idx < 16; idx++) {
            uint v = ((cb[0][0] >> idx) & 1u) << gid
                   | ((cb[0][1] >> idx) & 1u) << (gid + 8)
                   | ((cb[1][0] >> idx) & 1u) << (gid + 16)
                   | ((cb[1][1] >> idx) & 1u) << (gid + 24);
            v |= __shfl_xor_sync(0xffffffffu, v, 4);
            v |= __shfl_xor_sync(0xffffffffu, v, 8);
            v |= __shfl_xor_sync(0xffffffffu, v, 16);
            if (gid == 0) {
                int mg = m0 + wm * 64 + (idx >> 1) * 8 + 2 * lane + (idx & 1);
                g_adjT[((size_t)b * 128 + (n0 >> 5) + wn) * NNODE + mg] = v;
            }
        }
    }
}

// ---------------- fused degree + dinv + layer0 split ----------------
__global__ void __launch_bounds__(128) k_degsplit() {
    __shared__ int sc[4][32];
    __shared__ float sdv[32];

    int i0 = blockIdx.x * 32;
    int t = threadIdx.x, q = t >> 5, lane = t & 31;
    int gi = i0 + lane;
    int b = gi >> 12, nl = gi & 4095;
    const unsigned* base = g_adjT + (size_t)b * 128 * NNODE + nl;
    int c = 0;
    #pragma unroll 8
    for (int j = 0; j < 32; j++)
        c += __popc(base[(size_t)(q * 32 + j) * NNODE]);
    sc[q][lane] = c;
    __syncthreads();
    if (t < 32) {
        int tot = sc[0][t] + sc[1][t] + sc[2][t] + sc[3][t];
        float d = 1.0f / sqrtf((float)tot);
        g_dinv[i0 + t] = d;
        sdv[t] = d;
    }
    __syncthreads();

    int node = i0 + (t >> 2);
    float d = sdv[t >> 2];
    const float4* src = (const float4*)(g_xt + (size_t)node * 64 + (t & 3) * 16);
    unsigned short* o = g_xs + (size_t)node * 128 + (t & 3) * 16;
    #pragma unroll
    for (int j = 0; j < 4; j++) {
        float4 v = src[j];
        v.x *= d; v.y *= d; v.z *= d; v.w *= d;
        __nv_bfloat16 h0 = __float2bfloat16_rn(v.x);
        __nv_bfloat16 h1 = __float2bfloat16_rn(v.y);
        __nv_bfloat16 h2 = __float2bfloat16_rn(v.z);
        __nv_bfloat16 h3 = __float2bfloat16_rn(v.w);
        __nv_bfloat16 l0 = __float2bfloat16_rn(v.x - __bfloat162float(h0));
        __nv_bfloat16 l1 = __float2bfloat16_rn(v.y - __bfloat162float(h1));
        __nv_bfloat16 l2 = __float2bfloat16_rn(v.z - __bfloat162float(h2));
        __nv_bfloat16 l3 = __float2bfloat16_rn(v.w - __bfloat162float(h3));
        ushort4 hh, ll;
        hh.x = *(unsigned short*)&h0; hh.y = *(unsigned short*)&h1;
        hh.z = *(unsigned short*)&h2; hh.w = *(unsigned short*)&h3;
        ll.x = *(unsigned short*)&l0; ll.y = *(unsigned short*)&l1;
        ll.z = *(unsigned short*)&l2; ll.w = *(unsigned short*)&l3;
        *(ushort4*)(o + j * 4)      = hh;
        *(ushort4*)(o + 64 + j * 4) = ll;
    }
}

// ---------------- fused diffusion mma + FC + instance-norm + relu ----------------
__global__ void __launch_bounds__(128) k_mm(int layer, float* __restrict__ out_final,
                                            const float* __restrict__ W) {
    __shared__ union {
        unsigned short bs[2][64][SP];
        struct { float lxs[64][68]; float ws[64][64]; } e;
    } SM;

    int b = blockIdx.y, n0 = blockIdx.x * 64;
    int t = threadIdx.x, wr = t >> 5, lane = t & 31;
    int g = lane >> 2, tq = lane & 3;
    int rl8 = (lane & 7) + ((lane >> 3) & 1) * 8;
    int fg = (lane >> 4) * 8;

    const unsigned short* xsrc = (layer == 0) ? g_xs : g_xs2;
    const unsigned short* xsb = xsrc + (size_t)b * NNODE * 128;
    const unsigned* pa = g_adjT + (size_t)b * 128 * NNODE + (n0 + wr * 16 + g);
    const unsigned* pa8 = pa + 8;

    float cc[16][4];
    #pragma unroll
    for (int j = 0; j < 16; j++)
        #pragma unroll
        for (int q = 0; q < 4; q++) cc[j][q] = 0.f;

    int srow = t >> 4, schk = t & 15;
    uint sb0 = (uint)__cvta_generic_to_shared(&SM.bs[0][0][0]);
    uint sb1 = (uint)__cvta_generic_to_shared(&SM.bs[1][0][0]);

    float4 pf[8];
    #pragma unroll
    for (int ps = 0; ps < 8; ps++)
        pf[ps] = *(const float4*)(xsb + (size_t)(srow + ps * 8) * 128 + schk * 8);
    #pragma unroll
    for (int ps = 0; ps < 8; ps++)
        *(float4*)&SM.bs[0][srow + ps * 8][schk * 8] = pf[ps];
    #pragma unroll
    for (int ps = 0; ps < 8; ps++)
        pf[ps] = *(const float4*)(xsb + (size_t)(64 + srow + ps * 8) * 128 + schk * 8);
    unsigned w0a = pa[0], w1a = pa[(size_t)4096];
    unsigned w0b = pa8[0], w1b = pa8[(size_t)4096];

    for (int c = 0; c < 64; c++) {
        __syncthreads();
        if (c + 1 < 64) {
            #pragma unroll
            for (int ps = 0; ps < 8; ps++)
                *(float4*)&SM.bs[(c + 1) & 1][srow + ps * 8][schk * 8] = pf[ps];
            if (c + 2 < 64) {
                #pragma unroll
                for (int ps = 0; ps < 8; ps++)
                    pf[ps] = *(const float4*)(xsb + (size_t)((c + 2) * 64 + srow + ps * 8) * 128 + schk * 8);
            }
        }
        unsigned nw0a = 0, nw1a = 0, nw0b = 0, nw1b = 0;
        if (c + 1 < 64) {
            nw0a = pa[(size_t)(2 * c + 2) * 4096];
            nw1a = pa[(size_t)(2 * c + 3) * 4096];
            nw0b = pa8[(size_t)(2 * c + 2) * 4096];
            nw1b = pa8[(size_t)(2 * c + 3) * 4096];
        }
        uint bb = (c & 1) ? sb1 : sb0;
        #pragma unroll
        for (int q = 0; q < 4; q++) {
            unsigned wA = (q < 2) ? w0a : w1a;
            unsigned wB = (q < 2) ? w0b : w1b;
            int s = ((q & 1) << 4) + 2 * tq;
            uint a0 = bfpair((wA >> s) & 3u);
            uint a2 = bfpair((wA >> (s + 8)) & 3u);
            uint a1 = bfpair((wB >> s) & 3u);
            uint a3 = bfpair((wB >> (s + 8)) & 3u);
            uint baddr = bb + (uint)(((q * 16 + rl8) * SP + fg) * 2);
            #pragma unroll
            for (int p = 0; p < 8; p++) {
                uint r0, r1, r2, r3;
                asm volatile(
                    "ldmatrix.sync.aligned.m8n8.x4.trans.shared.b16 {%0,%1,%2,%3}, [%4];"
                    : "=r"(r0), "=r"(r1), "=r"(r2), "=r"(r3)
                    : "r"(baddr + (uint)(p * 32)));
                asm volatile(
                    "mma.sync.aligned.m16n8k16.row.col.f32.bf16.bf16.f32 "
                    "{%0,%1,%2,%3}, {%4,%5,%6,%7}, {%8,%9}, {%0,%1,%2,%3};"
                    : "+f"(cc[2 * p][0]), "+f"(cc[2 * p][1]), "+f"(cc[2 * p][2]), "+f"(cc[2 * p][3])
                    : "r"(a0), "r"(a1), "r"(a2), "r"(a3), "r"(r0), "r"(r1));
                asm volatile(
                    "mma.sync.aligned.m16n8k16.row.col.f32.bf16.bf16.f32 "
                    "{%0,%1,%2,%3}, {%4,%5,%6,%7}, {%8,%9}, {%0,%1,%2,%3};"
                    : "+f"(cc[2 * p + 1][0]), "+f"(cc[2 * p + 1][1]), "+f"(cc[2 * p + 1][2]), "+f"(cc[2 * p + 1][3])
                    : "r"(a0), "r"(a1), "r"(a2), "r"(a3), "r"(r2), "r"(r3));
            }
        }
        w0a = nw0a; w1a = nw1a; w0b = nw0b; w1b = nw1b;
    }
    __syncthreads();

    // epilogue: combine hi+lo, scale by dinv_n, stage lx
    {
        int lr0 = wr * 16 + g;
        float dn0 = g_dinv[b * NNODE + n0 + lr0];
        float dn1 = g_dinv[b * NNODE + n0 + lr0 + 8];
        #pragma unroll
        for (int j = 0; j < 8; j++) {
            int col = j * 8 + 2 * tq;
            float2 u0 = make_float2((cc[j][0] + cc[j + 8][0]) * dn0,
                                    (cc[j][1] + cc[j + 8][1]) * dn0);
            float2 u1 = make_float2((cc[j][2] + cc[j + 8][2]) * dn1,
                                    (cc[j][3] + cc[j + 8][3]) * dn1);
            *(float2*)&SM.e.lxs[lr0][col]     = u0;
            *(float2*)&SM.e.lxs[lr0 + 8][col] = u1;
        }
    }
    {
        int c2 = t >> 1, fh = (t & 1) * 32;
        #pragma unroll
        for (int j = 0; j < 8; j++)
            *(float4*)&SM.e.ws[c2][fh + j * 4] = *(const float4*)(W + c2 * 64 + fh + j * 4);
    }
    __syncthreads();

    int row = t >> 1, fh = (t & 1) * 32;
    ull h[16];
    #pragma unroll
    for (int j = 0; j < 16; j++) h[j] = 0ULL;
    #pragma unroll 8
    for (int c = 0; c < 64; c++) {
        ull a2 = pack2(SM.e.lxs[row][c]);
        const ulonglong2* w2 = (const ulonglong2*)&SM.e.ws[c][fh];
        #pragma unroll
        for (int j = 0; j < 4; j++) {
            ulonglong2 u0 = w2[2 * j];
            ulonglong2 u1 = w2[2 * j + 1];
            fma2(h[4 * j],     a2, u0.x);
            fma2(h[4 * j + 1], a2, u0.y);
            fma2(h[4 * j + 2], a2, u1.x);
            fma2(h[4 * j + 3], a2, u1.y);
        }
    }
    float hv[32];
    #pragma unroll
    for (int j = 0; j < 16; j++) { F2U u; u.u = h[j]; hv[2 * j] = u.f.x; hv[2 * j + 1] = u.f.y; }

    float sum = 0.f;
    #pragma unroll
    for (int j = 0; j < 32; j++) sum += hv[j];
    sum += __shfl_xor_sync(0xffffffffu, sum, 1);
    float mean = sum * (1.f / 64.f);
    float vq = 0.f;
    #pragma unroll
    for (int j = 0; j < 32; j++) { float d = hv[j] - mean; vq += d * d; }
    vq += __shfl_xor_sync(0xffffffffu, vq, 1);
    float inv = 1.0f / sqrtf(vq * (1.f / 64.f) + EPSI);

    int gnode = b * NNODE + n0 + row;
    if (layer == 0) {
        float d = g_dinv[gnode];
        unsigned short* o = g_xs2 + (size_t)gnode * 128 + fh;
        #pragma unroll
        for (int f4 = 0; f4 < 8; f4++) {
            ushort4 hh, ll;
            unsigned short* hp = &hh.x;
            unsigned short* lp = &ll.x;
            #pragma unroll
            for (int q = 0; q < 4; q++) {
                float y = fmaxf((hv[f4 * 4 + q] - mean) * inv, 0.f) * d;
                __nv_bfloat16 hb = __float2bfloat16_rn(y);
                __nv_bfloat16 lb = __float2bfloat16_rn(y - __bfloat162float(hb));
                hp[q] = *(unsigned short*)&hb;
                lp[q] = *(unsigned short*)&lb;
            }
            *(ushort4*)(o + f4 * 4)      = hh;
            *(ushort4*)(o + 64 + f4 * 4) = ll;
        }
    } else {
        float* op = out_final + (size_t)gnode * 64 + fh;
        #pragma unroll
        for (int f4 = 0; f4 < 8; f4++) {
            float4 ov;
            ov.x = fmaxf((hv[f4 * 4 + 0] - mean) * inv, 0.f);
            ov.y = fmaxf((hv[f4 * 4 + 1] - mean) * inv, 0.f);
            ov.z = fmaxf((hv[f4 * 4 + 2] - mean) * inv, 0.f);
            ov.w = fmaxf((hv[f4 * 4 + 3] - mean) * inv, 0.f);
            *(float4*)(op + f4 * 4) = ov;
        }
    }
}

// ---------------- launch ----------------
#define SMEM_GRAM (131072 + 1024)

extern "C" void kernel_launch(void* const* d_in, const int* in_sizes, int n_in,
                              void* d_out, int out_size) {
    const float* x  = (const float*)d_in[0];
    const float* W0 = (const float*)d_in[1];
    const float* W1 = (const float*)d_in[2];
    float* out = (float*)d_out;

    cudaFuncSetAttribute(k_gram, cudaFuncAttributeMaxDynamicSharedMemorySize, SMEM_GRAM);

    k_transpose<<<dim3(128, 2, 4), dim3(32, 8)>>>(x);
    k_prep<<<dim3(32, 4), 256>>>(x);
    k_gram<<<dim3(528, 4), 256, SMEM_GRAM>>>();
    k_degsplit<<<512, 128>>>();
    k_mm<<<dim3(64, 4), 128>>>(0, nullptr, W0);
    k_mm<<<dim3(64, 4), 128>>>(1, out, W1);
}

// round 10
// speedup vs baseline: 1.2775x; 1.0402x over previous
#include <cuda_runtime.h>
#include <cuda_bf16.h>
#include <math.h>

#define THR 0.005f
#define EPSI 1e-5f
#define NBATCH 4
#define NNODE 4096
#define NCH 64
#define SP 136   // padded bf16 row stride (272B) -> conflict-free ldmatrix

typedef unsigned long long ull;
typedef unsigned int uint;

// ---------------- device scratch ----------------
__device__ __align__(16) float g_xt[NBATCH * NNODE * NCH];     // x transposed [b][n][c]
__device__ __align__(16) float g_snorm[NBATCH * NNODE];
__device__ __align__(16) float g_dinv[NBATCH * NNODE];
__device__ __align__(16) unsigned g_adjT[NBATCH * 128 * NNODE];       // bits [b][word_m][n]
__device__ __align__(16) unsigned short g_xs [NBATCH * NNODE * 128];  // bf16 split layer0 in
__device__ __align__(16) unsigned short g_xs2[NBATCH * NNODE * 128];  // bf16 split layer1 in
// 3-way bf16 split planes, channel-major: [b][plane*64 + c][n], planes h,m,l
__device__ __align__(16) unsigned short g_xsp[NBATCH * 192 * NNODE];

// ---------------- helpers ----------------
__device__ __forceinline__ void fma2(ull& d, ull a, ull b) {
    asm("fma.rn.f32x2 %0, %1, %2, %0;" : "+l"(d) : "l"(a), "l"(b));
}
__device__ __forceinline__ ull pack2(float x) {
    ull r; asm("mov.b64 %0, {%1, %1};" : "=l"(r) : "f"(x)); return r;
}
union F2U { ull u; float2 f; };

__device__ __forceinline__ uint bfpair(uint u) {
    return ((u & 1u) ? 0x3F80u : 0u) | ((u & 2u) ? 0x3F800000u : 0u);
}

#define MMA_BF16(c, a0_, a1_, a2_, a3_, b0_, b1_) \
    asm volatile("mma.sync.aligned.m16n8k16.row.col.f32.bf16.bf16.f32 " \
        "{%0,%1,%2,%3},{%4,%5,%6,%7},{%8,%9},{%0,%1,%2,%3};" \
        : "+f"((c)[0]), "+f"((c)[1]), "+f"((c)[2]), "+f"((c)[3]) \
        : "r"(a0_), "r"(a1_), "r"(a2_), "r"(a3_), "r"(b0_), "r"(b1_))

// ---------------- transpose ----------------
__global__ void k_transpose(const float* __restrict__ x) {
    __shared__ float t[32][33];
    int b = blockIdx.z, c0 = blockIdx.y * 32, n0 = blockIdx.x * 32;
    int tx = threadIdx.x, ty = threadIdx.y;
    const float* xp = x + ((b * 64 + c0) * NNODE) + n0;
    #pragma unroll
    for (int i = ty; i < 32; i += 8) t[i][tx] = xp[i * NNODE + tx];
    __syncthreads();
    float* op = g_xt + ((b * NNODE + n0) * 64) + c0;
    #pragma unroll
    for (int i = ty; i < 32; i += 8) op[i * 64 + tx] = t[tx][i];
}

// ---------------- prep: 3-way bf16 split (channel-major) + node norms ----------------
__global__ void __launch_bounds__(128) k_prep(const float* __restrict__ x) {
    __shared__ float ps[2][64];
    int b = blockIdx.y;
    int t = threadIdx.x;
    int n = blockIdx.x * 64 + (t & 63);
    int half = t >> 6;
    int c0 = half * 32;

    const float* xb = x + (size_t)b * 64 * NNODE + n;
    unsigned short* op = g_xsp + (size_t)b * 192 * NNODE + n;

    float s = 0.f;
    #pragma unroll 8
    for (int c = c0; c < c0 + 32; c++) {
        float v = xb[(size_t)c * NNODE];
        s += v * v;
        __nv_bfloat16 h = __float2bfloat16_rn(v);
        float r1 = v - __bfloat162float(h);
        __nv_bfloat16 m = __float2bfloat16_rn(r1);
        float r2 = r1 - __bfloat162float(m);
        __nv_bfloat16 l = __float2bfloat16_rn(r2);
        op[(size_t)c * NNODE]         = *(unsigned short*)&h;
        op[(size_t)(64 + c) * NNODE]  = *(unsigned short*)&m;
        op[(size_t)(128 + c) * NNODE] = *(unsigned short*)&l;
    }
    ps[half][t & 63] = s;
    __syncthreads();
    if (t < 64) g_snorm[b * NNODE + blockIdx.x * 64 + t] = sqrtf(ps[0][t] + ps[1][t]);
}

// ---------------- Gram via bf16 mma, PAIR-stacked split (virtual K=320) -------
// Pair products (A-plane, B-plane): (h,h),(m,h),(h,m),(m,m),(l,h) -> captures all
// terms >= 2^-18 of x*x'. 10 chunks of 32 k-rows, double-buffered cp.async.
// Block 256 thr = 8 warps; tile 128n x 128m (triangular pairs). Warp 32n x 64m.
__global__ void __launch_bounds__(256) k_gram() {
    __shared__ __align__(16) unsigned short As[2][32][SP];
    __shared__ __align__(16) unsigned short Bs[2][32][SP];
    __shared__ float sns[128], sms[128];

    int b = blockIdx.y;
    int xid = blockIdx.x;
    int bj = (int)((sqrtf(8.f * xid + 1.f) - 1.f) * 0.5f);
    while ((bj + 1) * (bj + 2) / 2 <= xid) bj++;
    while (bj * (bj + 1) / 2 > xid) bj--;
    int bi = xid - bj * (bj + 1) / 2;
    int n0 = bi * 128, m0 = bj * 128;

    int t = threadIdx.x, warp = t >> 5, lane = t & 31;
    int wn = warp >> 1, wm = warp & 1;

    if (t < 128) sns[t] = g_snorm[b * NNODE + n0 + t];
    else         sms[t - 128] = g_snorm[b * NNODE + m0 + (t - 128)];

    const unsigned short* xp = g_xsp + (size_t)b * 192 * NNODE;
    int seg = t & 15, kr0 = t >> 4;      // seg: 16B col group, kr0: k row (0..15)

    uint sa = (uint)__cvta_generic_to_shared(&As[0][0][0]);
    uint sb = (uint)__cvta_generic_to_shared(&Bs[0][0][0]);
    const uint BUFB = 32 * SP * 2;

    // plane tables: pair p = kc>>1; A plane: p<4 ? p&1 : 2 ; B plane: (p>>1)&1
    #define STAGE(kc, buf) do { \
        int p_ = (kc) >> 1; \
        int pa_ = (p_ == 4) ? 2 : (p_ & 1); \
        int pb_ = (p_ >> 1) & 1; \
        int ka_ = pa_ * 64 + ((kc) & 1) * 32; \
        int kb_ = pb_ * 64 + ((kc) & 1) * 32; \
        uint da = sa + (buf) * BUFB; uint db = sb + (buf) * BUFB; \
        const unsigned short* a0_ = xp + (size_t)(ka_ + kr0) * NNODE + n0; \
        const unsigned short* a1_ = xp + (size_t)(ka_ + kr0 + 16) * NNODE + n0; \
        const unsigned short* b0_ = xp + (size_t)(kb_ + kr0) * NNODE + m0; \
        const unsigned short* b1_ = xp + (size_t)(kb_ + kr0 + 16) * NNODE + m0; \
        asm volatile("cp.async.ca.shared.global [%0], [%1], 16;" \
            :: "r"(da + (uint)(kr0 * SP + seg * 8) * 2),        "l"(a0_ + seg * 8)); \
        asm volatile("cp.async.ca.shared.global [%0], [%1], 16;" \
            :: "r"(da + (uint)((kr0 + 16) * SP + seg * 8) * 2), "l"(a1_ + seg * 8)); \
        asm volatile("cp.async.ca.shared.global [%0], [%1], 16;" \
            :: "r"(db + (uint)(kr0 * SP + seg * 8) * 2),        "l"(b0_ + seg * 8)); \
        asm volatile("cp.async.ca.shared.global [%0], [%1], 16;" \
            :: "r"(db + (uint)((kr0 + 16) * SP + seg * 8) * 2), "l"(b1_ + seg * 8)); \
        asm volatile("cp.async.commit_group;"); \
    } while (0)

    float cc[2][8][4];
    #pragma unroll
    for (int t2 = 0; t2 < 2; t2++)
        #pragma unroll
        for (int j = 0; j < 8; j++)
            #pragma unroll
            for (int q = 0; q < 4; q++) cc[t2][j][q] = 0.f;

    STAGE(0, 0);
    STAGE(1, 1);

    int krl = (lane & 7) + ((lane >> 3) & 1) * 8;   // ldmatrix row-within-k16
    int chalf = (lane >> 4) * 8;                    // 8-node column half

    for (int kc = 0; kc < 10; kc++) {
        if (kc < 9) asm volatile("cp.async.wait_group 1;" ::: "memory");
        else        asm volatile("cp.async.wait_group 0;" ::: "memory");
        __syncthreads();
        int buf = kc & 1;
        uint ab = sa + buf * BUFB;
        uint bb = sb + buf * BUFB;
        #pragma unroll
        for (int ks = 0; ks < 2; ks++) {
            int kr = ks * 16 + krl;
            uint a[2][4];
            #pragma unroll
            for (int t2 = 0; t2 < 2; t2++) {
                uint addr = ab + (uint)(kr * SP + wn * 32 + t2 * 16 + chalf) * 2;
                asm volatile(
                    "ldmatrix.sync.aligned.m8n8.x4.trans.shared.b16 {%0,%1,%2,%3}, [%4];"
                    : "=r"(a[t2][0]), "=r"(a[t2][1]), "=r"(a[t2][2]), "=r"(a[t2][3])
                    : "r"(addr));
            }
            #pragma unroll
            for (int mg = 0; mg < 4; mg++) {
                uint r0, r1, r2, r3;
                uint addr = bb + (uint)(kr * SP + wm * 64 + mg * 16 + chalf) * 2;
                asm volatile(
                    "ldmatrix.sync.aligned.m8n8.x4.trans.shared.b16 {%0,%1,%2,%3}, [%4];"
                    : "=r"(r0), "=r"(r1), "=r"(r2), "=r"(r3)
                    : "r"(addr));
                #pragma unroll
                for (int t2 = 0; t2 < 2; t2++) {
                    MMA_BF16(cc[t2][2 * mg],     a[t2][0], a[t2][2], a[t2][1], a[t2][3], r0, r1);
                    MMA_BF16(cc[t2][2 * mg + 1], a[t2][0], a[t2][2], a[t2][1], a[t2][3], r2, r3);
                }
            }
        }
        __syncthreads();
        if (kc + 2 < 10) STAGE(kc + 2, buf);
    }

    // ---- threshold + bit packing (both orientations; diagonal skips transposed) ----
    int q = lane & 3, gid = lane >> 2;
    uint cb[2][2];
    #pragma unroll
    for (int t2 = 0; t2 < 2; t2++) {
        #pragma unroll
        for (int rh = 0; rh < 2; rh++) {
            int rl = wn * 32 + t2 * 16 + rh * 8 + gid;
            float sn = sns[rl];
            uint c = 0;
            #pragma unroll
            for (int j = 0; j < 8; j++) {
                int ml = wm * 64 + j * 8 + 2 * q;
                uint c0 = (cc[t2][j][rh * 2]     > THR * (sn * sms[ml]))     ? 1u : 0u;
                uint c1 = (cc[t2][j][rh * 2 + 1] > THR * (sn * sms[ml + 1])) ? 1u : 0u;
                c |= (c0 << (2 * j)) | (c1 << (2 * j + 1));
            }
            cb[t2][rh] = c;
            uint w0 = 0, w1 = 0;
            #pragma unroll
            for (int j = 0; j < 4; j++) {
                w0 |= ((c >> (2 * j)) & 1u)     << (j * 8 + 2 * q);
                w0 |= ((c >> (2 * j + 1)) & 1u) << (j * 8 + 2 * q + 1);
                w1 |= ((c >> (2 * j + 8)) & 1u) << (j * 8 + 2 * q);
                w1 |= ((c >> (2 * j + 9)) & 1u) << (j * 8 + 2 * q + 1);
            }
            w0 |= __shfl_xor_sync(0xffffffffu, w0, 1);
            w0 |= __shfl_xor_sync(0xffffffffu, w0, 2);
            w1 |= __shfl_xor_sync(0xffffffffu, w1, 1);
            w1 |= __shfl_xor_sync(0xffffffffu, w1, 2);
            if (q == 0) {
                int gn = n0 + rl;
                g_adjT[((size_t)b * 128 + (m0 >> 5) + wm * 2)     * NNODE + gn] = w0;
                g_adjT[((size_t)b * 128 + (m0 >> 5) + wm * 2 + 1) * NNODE + gn] = w1;
            }
        }
    }
    if (bi != bj) {
        #pragma unroll
        for (int idx = 0; idx < 16; idx++) {
            uint v = ((cb[0][0] >> idx) & 1u) << gid
                   | ((cb[0][1] >> idx) & 1u) << (gid + 8)
                   | ((cb[1][0] >> idx) & 1u) << (gid + 16)
                   | ((cb[1][1] >> idx) & 1u) << (gid + 24);
            v |= __shfl_xor_sync(0xffffffffu, v, 4);
            v |= __shfl_xor_sync(0xffffffffu, v, 8);
            v |= __shfl_xor_sync(0xffffffffu, v, 16);
            if (gid == 0) {
                int mg = m0 + wm * 64 + (idx >> 1) * 8 + 2 * lane + (idx & 1);
                g_adjT[((size_t)b * 128 + (n0 >> 5) + wn) * NNODE + mg] = v;
            }
        }
    }
}

// ---------------- fused degree + dinv + layer0 split ----------------
__global__ void __launch_bounds__(128) k_degsplit() {
    __shared__ int sc[4][32];
    __shared__ float sdv[32];

    int i0 = blockIdx.x * 32;
    int t = threadIdx.x, q = t >> 5, lane = t & 31;
    int gi = i0 + lane;
    int b = gi >> 12, nl = gi & 4095;
    const unsigned* base = g_adjT + (size_t)b * 128 * NNODE + nl;
    int c = 0;
    #pragma unroll 8
    for (int j = 0; j < 32; j++)
        c += __popc(base[(size_t)(q * 32 + j) * NNODE]);
    sc[q][lane] = c;
    __syncthreads();
    if (t < 32) {
        int tot = sc[0][t] + sc[1][t] + sc[2][t] + sc[3][t];
        float d = 1.0f / sqrtf((float)tot);
        g_dinv[i0 + t] = d;
        sdv[t] = d;
    }
    __syncthreads();

    int node = i0 + (t >> 2);
    float d = sdv[t >> 2];
    const float4* src = (const float4*)(g_xt + (size_t)node * 64 + (t & 3) * 16);
    unsigned short* o = g_xs + (size_t)node * 128 + (t & 3) * 16;
    #pragma unroll
    for (int j = 0; j < 4; j++) {
        float4 v = src[j];
        v.x *= d; v.y *= d; v.z *= d; v.w *= d;
        __nv_bfloat16 h0 = __float2bfloat16_rn(v.x);
        __nv_bfloat16 h1 = __float2bfloat16_rn(v.y);
        __nv_bfloat16 h2 = __float2bfloat16_rn(v.z);
        __nv_bfloat16 h3 = __float2bfloat16_rn(v.w);
        __nv_bfloat16 l0 = __float2bfloat16_rn(v.x - __bfloat162float(h0));
        __nv_bfloat16 l1 = __float2bfloat16_rn(v.y - __bfloat162float(h1));
        __nv_bfloat16 l2 = __float2bfloat16_rn(v.z - __bfloat162float(h2));
        __nv_bfloat16 l3 = __float2bfloat16_rn(v.w - __bfloat162float(h3));
        ushort4 hh, ll;
        hh.x = *(unsigned short*)&h0; hh.y = *(unsigned short*)&h1;
        hh.z = *(unsigned short*)&h2; hh.w = *(unsigned short*)&h3;
        ll.x = *(unsigned short*)&l0; ll.y = *(unsigned short*)&l1;
        ll.z = *(unsigned short*)&l2; ll.w = *(unsigned short*)&l3;
        *(ushort4*)(o + j * 4)      = hh;
        *(ushort4*)(o + 64 + j * 4) = ll;
    }
}

// ---------------- fused diffusion mma + FC + instance-norm + relu ----------------
__global__ void __launch_bounds__(128) k_mm(int layer, float* __restrict__ out_final,
                                            const float* __restrict__ W) {
    __shared__ union {
        unsigned short bs[2][64][SP];
        struct { float lxs[64][68]; float ws[64][64]; } e;
    } SM;

    int b = blockIdx.y, n0 = blockIdx.x * 64;
    int t = threadIdx.x, wr = t >> 5, lane = t & 31;
    int g = lane >> 2, tq = lane & 3;
    int rl8 = (lane & 7) + ((lane >> 3) & 1) * 8;
    int fg = (lane >> 4) * 8;

    const unsigned short* xsrc = (layer == 0) ? g_xs : g_xs2;
    const unsigned short* xsb = xsrc + (size_t)b * NNODE * 128;
    const unsigned* pa = g_adjT + (size_t)b * 128 * NNODE + (n0 + wr * 16 + g);
    const unsigned* pa8 = pa + 8;

    float cc[16][4];
    #pragma unroll
    for (int j = 0; j < 16; j++)
        #pragma unroll
        for (int q = 0; q < 4; q++) cc[j][q] = 0.f;

    int srow = t >> 4, schk = t & 15;
    uint sb0 = (uint)__cvta_generic_to_shared(&SM.bs[0][0][0]);
    uint sb1 = (uint)__cvta_generic_to_shared(&SM.bs[1][0][0]);

    float4 pf[8];
    #pragma unroll
    for (int ps = 0; ps < 8; ps++)
        pf[ps] = *(const float4*)(xsb + (size_t)(srow + ps * 8) * 128 + schk * 8);
    #pragma unroll
    for (int ps = 0; ps < 8; ps++)
        *(float4*)&SM.bs[0][srow + ps * 8][schk * 8] = pf[ps];
    #pragma unroll
    for (int ps = 0; ps < 8; ps++)
        pf[ps] = *(const float4*)(xsb + (size_t)(64 + srow + ps * 8) * 128 + schk * 8);
    unsigned w0a = pa[0], w1a = pa[(size_t)4096];
    unsigned w0b = pa8[0], w1b = pa8[(size_t)4096];

    for (int c = 0; c < 64; c++) {
        __syncthreads();
        if (c + 1 < 64) {
            #pragma unroll
            for (int ps = 0; ps < 8; ps++)
                *(float4*)&SM.bs[(c + 1) & 1][srow + ps * 8][schk * 8] = pf[ps];
            if (c + 2 < 64) {
                #pragma unroll
                for (int ps = 0; ps < 8; ps++)
                    pf[ps] = *(const float4*)(xsb + (size_t)((c + 2) * 64 + srow + ps * 8) * 128 + schk * 8);
            }
        }
        unsigned nw0a = 0, nw1a = 0, nw0b = 0, nw1b = 0;
        if (c + 1 < 64) {
            nw0a = pa[(size_t)(2 * c + 2) * 4096];
            nw1a = pa[(size_t)(2 * c + 3) * 4096];
            nw0b = pa8[(size_t)(2 * c + 2) * 4096];
            nw1b = pa8[(size_t)(2 * c + 3) * 4096];
        }
        uint bb = (c & 1) ? sb1 : sb0;
        #pragma unroll
        for (int q = 0; q < 4; q++) {
            unsigned wA = (q < 2) ? w0a : w1a;
            unsigned wB = (q < 2) ? w0b : w1b;
            int s = ((q & 1) << 4) + 2 * tq;
            uint a0 = bfpair((wA >> s) & 3u);
            uint a2 = bfpair((wA >> (s + 8)) & 3u);
            uint a1 = bfpair((wB >> s) & 3u);
            uint a3 = bfpair((wB >> (s + 8)) & 3u);
            uint baddr = bb + (uint)(((q * 16 + rl8) * SP + fg) * 2);
            #pragma unroll
            for (int p = 0; p < 8; p++) {
                uint r0, r1, r2, r3;
                asm volatile(
                    "ldmatrix.sync.aligned.m8n8.x4.trans.shared.b16 {%0,%1,%2,%3}, [%4];"
                    : "=r"(r0), "=r"(r1), "=r"(r2), "=r"(r3)
                    : "r"(baddr + (uint)(p * 32)));
                MMA_BF16(cc[2 * p],     a0, a1, a2, a3, r0, r1);
                MMA_BF16(cc[2 * p + 1], a0, a1, a2, a3, r2, r3);
            }
        }
        w0a = nw0a; w1a = nw1a; w0b = nw0b; w1b = nw1b;
    }
    __syncthreads();

    {
        int lr0 = wr * 16 + g;
        float dn0 = g_dinv[b * NNODE + n0 + lr0];
        float dn1 = g_dinv[b * NNODE + n0 + lr0 + 8];
        #pragma unroll
        for (int j = 0; j < 8; j++) {
            int col = j * 8 + 2 * tq;
            float2 u0 = make_float2((cc[j][0] + cc[j + 8][0]) * dn0,
                                    (cc[j][1] + cc[j + 8][1]) * dn0);
            float2 u1 = make_float2((cc[j][2] + cc[j + 8][2]) * dn1,
                                    (cc[j][3] + cc[j + 8][3]) * dn1);
            *(float2*)&SM.e.lxs[lr0][col]     = u0;
            *(float2*)&SM.e.lxs[lr0 + 8][col] = u1;
        }
    }
    {
        int c2 = t >> 1, fh = (t & 1) * 32;
        #pragma unroll
        for (int j = 0; j < 8; j++)
            *(float4*)&SM.e.ws[c2][fh + j * 4] = *(const float4*)(W + c2 * 64 + fh + j * 4);
    }
    __syncthreads();

    int row = t >> 1, fh = (t & 1) * 32;
    ull h[16];
    #pragma unroll
    for (int j = 0; j < 16; j++) h[j] = 0ULL;
    #pragma unroll 8
    for (int c = 0; c < 64; c++) {
        ull a2 = pack2(SM.e.lxs[row][c]);
        const ulonglong2* w2 = (const ulonglong2*)&SM.e.ws[c][fh];
        #pragma unroll
        for (int j = 0; j < 4; j++) {
            ulonglong2 u0 = w2[2 * j];
            ulonglong2 u1 = w2[2 * j + 1];
            fma2(h[4 * j],     a2, u0.x);
            fma2(h[4 * j + 1], a2, u0.y);
            fma2(h[4 * j + 2], a2, u1.x);
            fma2(h[4 * j + 3], a2, u1.y);
        }
    }
    float hv[32];
    #pragma unroll
    for (int j = 0; j < 16; j++) { F2U u; u.u = h[j]; hv[2 * j] = u.f.x; hv[2 * j + 1] = u.f.y; }

    float sum = 0.f;
    #pragma unroll
    for (int j = 0; j < 32; j++) sum += hv[j];
    sum += __shfl_xor_sync(0xffffffffu, sum, 1);
    float mean = sum * (1.f / 64.f);
    float vq = 0.f;
    #pragma unroll
    for (int j = 0; j < 32; j++) { float d = hv[j] - mean; vq += d * d; }
    vq += __shfl_xor_sync(0xffffffffu, vq, 1);
    float inv = 1.0f / sqrtf(vq * (1.f / 64.f) + EPSI);

    int gnode = b * NNODE + n0 + row;
    if (layer == 0) {
        float d = g_dinv[gnode];
        unsigned short* o = g_xs2 + (size_t)gnode * 128 + fh;
        #pragma unroll
        for (int f4 = 0; f4 < 8; f4++) {
            ushort4 hh, ll;
            unsigned short* hp = &hh.x;
            unsigned short* lp = &ll.x;
            #pragma unroll
            for (int q = 0; q < 4; q++) {
                float y = fmaxf((hv[f4 * 4 + q] - mean) * inv, 0.f) * d;
                __nv_bfloat16 hb = __float2bfloat16_rn(y);
                __nv_bfloat16 lb = __float2bfloat16_rn(y - __bfloat162float(hb));
                hp[q] = *(unsigned short*)&hb;
                lp[q] = *(unsigned short*)&lb;
            }
            *(ushort4*)(o + f4 * 4)      = hh;
            *(ushort4*)(o + 64 + f4 * 4) = ll;
        }
    } else {
        float* op = out_final + (size_t)gnode * 64 + fh;
        #pragma unroll
        for (int f4 = 0; f4 < 8; f4++) {
            float4 ov;
            ov.x = fmaxf((hv[f4 * 4 + 0] - mean) * inv, 0.f);
            ov.y = fmaxf((hv[f4 * 4 + 1] - mean) * inv, 0.f);
            ov.z = fmaxf((hv[f4 * 4 + 2] - mean) * inv, 0.f);
            ov.w = fmaxf((hv[f4 * 4 + 3] - mean) * inv, 0.f);
            *(float4*)(op + f4 * 4) = ov;
        }
    }
}

// ---------------- launch ----------------
extern "C" void kernel_launch(void* const* d_in, const int* in_sizes, int n_in,
                              void* d_out, int out_size) {
    const float* x  = (const float*)d_in[0];
    const float* W0 = (const float*)d_in[1];
    const float* W1 = (const float*)d_in[2];
    float* out = (float*)d_out;

    k_transpose<<<dim3(128, 2, 4), dim3(32, 8)>>>(x);
    k_prep<<<dim3(64, 4), 128>>>(x);
    k_gram<<<dim3(528, 4), 256>>>();
    k_degsplit<<<512, 128>>>();
    k_mm<<<dim3(64, 4), 128>>>(0, nullptr, W0);
    k_mm<<<dim3(64, 4), 128>>>(1, out, W1);
}

// round 12
// speedup vs baseline: 1.3341x; 1.0442x over previous
#include <cuda_runtime.h>
#include <cuda_bf16.h>
#include <math.h>

#define THR 0.005f
#define EPSI 1e-5f
#define NBATCH 4
#define NNODE 4096
#define NCH 64
#define SP 136   // padded bf16 row stride (272B) -> conflict-free ldmatrix

typedef unsigned long long ull;
typedef unsigned int uint;

// ---------------- device scratch ----------------
__device__ __align__(16) float g_xt[NBATCH * NNODE * NCH];     // x transposed [b][n][c]
__device__ __align__(16) float g_snorm[NBATCH * NNODE];
__device__ __align__(16) float g_dinv[NBATCH * NNODE];
__device__ __align__(16) unsigned g_adjT[NBATCH * 128 * NNODE];       // bits [b][word_m][n]
__device__ __align__(16) unsigned short g_xs [NBATCH * NNODE * 128];  // bf16 split layer0 in
__device__ __align__(16) unsigned short g_xs2[NBATCH * NNODE * 128];  // bf16 split layer1 in
// 3-way bf16 split planes, channel-major: [b][plane*64 + c][n], planes h,m,l
__device__ __align__(16) unsigned short g_xsp[NBATCH * 192 * NNODE];

// ---------------- helpers ----------------
__device__ __forceinline__ void fma2(ull& d, ull a, ull b) {
    asm("fma.rn.f32x2 %0, %1, %2, %0;" : "+l"(d) : "l"(a), "l"(b));
}
__device__ __forceinline__ ull pack2(float x) {
    ull r; asm("mov.b64 %0, {%1, %1};" : "=l"(r) : "f"(x)); return r;
}
union F2U { ull u; float2 f; };

__device__ __forceinline__ uint bfpair(uint u) {
    return ((u & 1u) ? 0x3F80u : 0u) | ((u & 2u) ? 0x3F800000u : 0u);
}

#define MMA_BF16(c, a0_, a1_, a2_, a3_, b0_, b1_) \
    asm volatile("mma.sync.aligned.m16n8k16.row.col.f32.bf16.bf16.f32 " \
        "{%0,%1,%2,%3},{%4,%5,%6,%7},{%8,%9},{%0,%1,%2,%3};" \
        : "+f"((c)[0]), "+f"((c)[1]), "+f"((c)[2]), "+f"((c)[3]) \
        : "r"(a0_), "r"(a1_), "r"(a2_), "r"(a3_), "r"(b0_), "r"(b1_))

// ---------------- prep: transpose + node norms + 3-way bf16 split ----------------
// Block: 64 nodes x 64 channels, 256 threads. Produces g_xt (node-major float),
// g_snorm, and channel-major split planes g_xsp.
__global__ void __launch_bounds__(256) k_prep(const float* __restrict__ x) {
    __shared__ float xs2[64][65];   // [node][channel]
    int b = blockIdx.y, n0 = blockIdx.x * 64;
    int t = threadIdx.x;
    int c = t >> 2, seg = t & 3;
    {
        const float* xp = x + (size_t)(b * 64 + c) * NNODE + n0 + seg * 16;
        #pragma unroll
        for (int j = 0; j < 16; j++) xs2[seg * 16 + j][c] = xp[j];
    }
    __syncthreads();

    if (t < 64) {
        float s = 0.f;
        #pragma unroll
        for (int cc = 0; cc < 64; cc++) { float v = xs2[t][cc]; s += v * v; }
        g_snorm[b * NNODE + n0 + t] = sqrtf(s);
    }

    // write g_xt node-major (node = t>>2, quad = t&3)
    {
        int node = t >> 2, q = t & 3;
        float* op = g_xt + (size_t)(b * NNODE + n0 + node) * 64 + q * 16;
        #pragma unroll
        for (int j4 = 0; j4 < 4; j4++) {
            float4 v;
            v.x = xs2[node][q * 16 + j4 * 4 + 0];
            v.y = xs2[node][q * 16 + j4 * 4 + 1];
            v.z = xs2[node][q * 16 + j4 * 4 + 2];
            v.w = xs2[node][q * 16 + j4 * 4 + 3];
            *(float4*)(op + j4 * 4) = v;
        }
    }

    // write channel-major splits: thread owns (channel c, 16 nodes seg*16..)
    {
        unsigned short hb[16], mb[16], lb[16];
        #pragma unroll
        for (int j = 0; j < 16; j++) {
            float v = xs2[seg * 16 + j][c];
            __nv_bfloat16 h = __float2bfloat16_rn(v);
            float r1 = v - __bfloat162float(h);
            __nv_bfloat16 m = __float2bfloat16_rn(r1);
            __nv_bfloat16 l = __float2bfloat16_rn(r1 - __bfloat162float(m));
            hb[j] = *(unsigned short*)&h;
            mb[j] = *(unsigned short*)&m;
            lb[j] = *(unsigned short*)&l;
        }
        unsigned short* op = g_xsp + ((size_t)b * 192 + c) * NNODE + n0 + seg * 16;
        const size_t PL = (size_t)64 * NNODE;
        #pragma unroll
        for (int j4 = 0; j4 < 4; j4++) {
            *(ushort4*)(op + j4 * 4)          = *(ushort4*)&hb[j4 * 4];
            *(ushort4*)(op + PL + j4 * 4)     = *(ushort4*)&mb[j4 * 4];
            *(ushort4*)(op + 2 * PL + j4 * 4) = *(ushort4*)&lb[j4 * 4];
        }
    }
}

// ---------------- Gram via bf16 mma, PAIR-stacked split (virtual K=256) -------
// Pairs (A-plane,B-plane): (h,h),(m,h),(h,m),(m,m) == exact (h+m)(h'+m')^T.
// Missing terms are l-sided (~2^-17) -> rel_err ~1e-4. 8 chunks of 32 k-rows,
// double-buffered cp.async. Block 256 thr = 8 warps; tile 128n x 128m
// (triangular pairs). Warp 32n x 64m.
__global__ void __launch_bounds__(256) k_gram() {
    __shared__ __align__(16) unsigned short As[2][32][SP];
    __shared__ __align__(16) unsigned short Bs[2][32][SP];
    __shared__ float sns[128], sms[128];

    int b = blockIdx.y;
    int xid = blockIdx.x;
    int bj = (int)((sqrtf(8.f * xid + 1.f) - 1.f) * 0.5f);
    while ((bj + 1) * (bj + 2) / 2 <= xid) bj++;
    while (bj * (bj + 1) / 2 > xid) bj--;
    int bi = xid - bj * (bj + 1) / 2;
    int n0 = bi * 128, m0 = bj * 128;

    int t = threadIdx.x, warp = t >> 5, lane = t & 31;
    int wn = warp >> 1, wm = warp & 1;

    if (t < 128) sns[t] = g_snorm[b * NNODE + n0 + t];
    else         sms[t - 128] = g_snorm[b * NNODE + m0 + (t - 128)];

    const unsigned short* xp = g_xsp + (size_t)b * 192 * NNODE;
    int seg = t & 15, kr0 = t >> 4;      // seg: 16B col group, kr0: k row (0..15)

    uint sa = (uint)__cvta_generic_to_shared(&As[0][0][0]);
    uint sb = (uint)__cvta_generic_to_shared(&Bs[0][0][0]);
    const uint BUFB = 32 * SP * 2;

    // pair p = kc>>1: A plane = p&1 (h,m,h,m), B plane = p>>1 (h,h,m,m)
    #define STAGE(kc, buf) do { \
        int p_ = (kc) >> 1; \
        int ka_ = (p_ & 1) * 64 + ((kc) & 1) * 32; \
        int kb_ = ((p_ >> 1) & 1) * 64 + ((kc) & 1) * 32; \
        uint da = sa + (buf) * BUFB; uint db = sb + (buf) * BUFB; \
        const unsigned short* a0_ = xp + (size_t)(ka_ + kr0) * NNODE + n0; \
        const unsigned short* a1_ = xp + (size_t)(ka_ + kr0 + 16) * NNODE + n0; \
        const unsigned short* b0_ = xp + (size_t)(kb_ + kr0) * NNODE + m0; \
        const unsigned short* b1_ = xp + (size_t)(kb_ + kr0 + 16) * NNODE + m0; \
        asm volatile("cp.async.ca.shared.global [%0], [%1], 16;" \
            :: "r"(da + (uint)(kr0 * SP + seg * 8) * 2),        "l"(a0_ + seg * 8)); \
        asm volatile("cp.async.ca.shared.global [%0], [%1], 16;" \
            :: "r"(da + (uint)((kr0 + 16) * SP + seg * 8) * 2), "l"(a1_ + seg * 8)); \
        asm volatile("cp.async.ca.shared.global [%0], [%1], 16;" \
            :: "r"(db + (uint)(kr0 * SP + seg * 8) * 2),        "l"(b0_ + seg * 8)); \
        asm volatile("cp.async.ca.shared.global [%0], [%1], 16;" \
            :: "r"(db + (uint)((kr0 + 16) * SP + seg * 8) * 2), "l"(b1_ + seg * 8)); \
        asm volatile("cp.async.commit_group;"); \
    } while (0)

    float cc[2][8][4];
    #pragma unroll
    for (int t2 = 0; t2 < 2; t2++)
        #pragma unroll
        for (int j = 0; j < 8; j++)
            #pragma unroll
            for (int q = 0; q < 4; q++) cc[t2][j][q] = 0.f;

    STAGE(0, 0);
    STAGE(1, 1);

    int krl = (lane & 7) + ((lane >> 3) & 1) * 8;   // ldmatrix row-within-k16
    int chalf = (lane >> 4) * 8;                    // 8-node column half

    for (int kc = 0; kc < 8; kc++) {
        if (kc < 7) asm volatile("cp.async.wait_group 1;" ::: "memory");
        else        asm volatile("cp.async.wait_group 0;" ::: "memory");
        __syncthreads();
        int buf = kc & 1;
        uint ab = sa + buf * BUFB;
        uint bb = sb + buf * BUFB;
        #pragma unroll
        for (int ks = 0; ks < 2; ks++) {
            int kr = ks * 16 + krl;
            uint a[2][4];
            #pragma unroll
            for (int t2 = 0; t2 < 2; t2++) {
                uint addr = ab + (uint)(kr * SP + wn * 32 + t2 * 16 + chalf) * 2;
                asm volatile(
                    "ldmatrix.sync.aligned.m8n8.x4.trans.shared.b16 {%0,%1,%2,%3}, [%4];"
                    : "=r"(a[t2][0]), "=r"(a[t2][1]), "=r"(a[t2][2]), "=r"(a[t2][3])
                    : "r"(addr));
            }
            #pragma unroll
            for (int mg = 0; mg < 4; mg++) {
                uint r0, r1, r2, r3;
                uint addr = bb + (uint)(kr * SP + wm * 64 + mg * 16 + chalf) * 2;
                asm volatile(
                    "ldmatrix.sync.aligned.m8n8.x4.trans.shared.b16 {%0,%1,%2,%3}, [%4];"
                    : "=r"(r0), "=r"(r1), "=r"(r2), "=r"(r3)
                    : "r"(addr));
                #pragma unroll
                for (int t2 = 0; t2 < 2; t2++) {
                    MMA_BF16(cc[t2][2 * mg],     a[t2][0], a[t2][2], a[t2][1], a[t2][3], r0, r1);
                    MMA_BF16(cc[t2][2 * mg + 1], a[t2][0], a[t2][2], a[t2][1], a[t2][3], r2, r3);
                }
            }
        }
        __syncthreads();
        if (kc + 2 < 8) STAGE(kc + 2, buf);
    }

    // ---- threshold + bit packing (both orientations; diagonal skips transposed) ----
    int q = lane & 3, gid = lane >> 2;
    uint cb[2][2];
    #pragma unroll
    for (int t2 = 0; t2 < 2; t2++) {
        #pragma unroll
        for (int rh = 0; rh < 2; rh++) {
            int rl = wn * 32 + t2 * 16 + rh * 8 + gid;
            float sn = sns[rl];
            uint c = 0;
            #pragma unroll
            for (int j = 0; j < 8; j++) {
                int ml = wm * 64 + j * 8 + 2 * q;
                uint c0 = (cc[t2][j][rh * 2]     > THR * (sn * sms[ml]))     ? 1u : 0u;
                uint c1 = (cc[t2][j][rh * 2 + 1] > THR * (sn * sms[ml + 1])) ? 1u : 0u;
                c |= (c0 << (2 * j)) | (c1 << (2 * j + 1));
            }
            cb[t2][rh] = c;
            uint w0 = 0, w1 = 0;
            #pragma unroll
            for (int j = 0; j < 4; j++) {
                w0 |= ((c >> (2 * j)) & 1u)     << (j * 8 + 2 * q);
                w0 |= ((c >> (2 * j + 1)) & 1u) << (j * 8 + 2 * q + 1);
                w1 |= ((c >> (2 * j + 8)) & 1u) << (j * 8 + 2 * q);
                w1 |= ((c >> (2 * j + 9)) & 1u) << (j * 8 + 2 * q + 1);
            }
            w0 |= __shfl_xor_sync(0xffffffffu, w0, 1);
            w0 |= __shfl_xor_sync(0xffffffffu, w0, 2);
            w1 |= __shfl_xor_sync(0xffffffffu, w1, 1);
            w1 |= __shfl_xor_sync(0xffffffffu, w1, 2);
            if (q == 0) {
                int gn = n0 + rl;
                g_adjT[((size_t)b * 128 + (m0 >> 5) + wm * 2)     * NNODE + gn] = w0;
                g_adjT[((size_t)b * 128 + (m0 >> 5) + wm * 2 + 1) * NNODE + gn] = w1;
            }
        }
    }
    if (bi != bj) {
        #pragma unroll
        for (int idx = 0; idx < 16; idx++) {
            uint v = ((cb[0][0] >> idx) & 1u) << gid
                   | ((cb[0][1] >> idx) & 1u) << (gid + 8)
                   | ((cb[1][0] >> idx) & 1u) << (gid + 16)
                   | ((cb[1][1] >> idx) & 1u) << (gid + 24);
            v |= __shfl_xor_sync(0xffffffffu, v, 4);
            v |= __shfl_xor_sync(0xffffffffu, v, 8);
            v |= __shfl_xor_sync(0xffffffffu, v, 16);
            if (gid == 0) {
                int mg = m0 + wm * 64 + (idx >> 1) * 8 + 2 * lane + (idx & 1);
                g_adjT[((size_t)b * 128 + (n0 >> 5) + wn) * NNODE + mg] = v;
            }
        }
    }
}

// ---------------- fused degree + dinv + layer0 split ----------------
__global__ void __launch_bounds__(128) k_degsplit() {
    __shared__ int sc[4][32];
    __shared__ float sdv[32];

    int i0 = blockIdx.x * 32;
    int t = threadIdx.x, q = t >> 5, lane = t & 31;
    int gi = i0 + lane;
    int b = gi >> 12, nl = gi & 4095;
    const unsigned* base = g_adjT + (size_t)b * 128 * NNODE + nl;
    int c = 0;
    #pragma unroll 8
    for (int j = 0; j < 32; j++)
        c += __popc(base[(size_t)(q * 32 + j) * NNODE]);
    sc[q][lane] = c;
    __syncthreads();
    if (t < 32) {
        int tot = sc[0][t] + sc[1][t] + sc[2][t] + sc[3][t];
        float d = 1.0f / sqrtf((float)tot);
        g_dinv[i0 + t] = d;
        sdv[t] = d;
    }
    __syncthreads();

    int node = i0 + (t >> 2);
    float d = sdv[t >> 2];
    const float4* src = (const float4*)(g_xt + (size_t)node * 64 + (t & 3) * 16);
    unsigned short* o = g_xs + (size_t)node * 128 + (t & 3) * 16;
    #pragma unroll
    for (int j = 0; j < 4; j++) {
        float4 v = src[j];
        v.x *= d; v.y *= d; v.z *= d; v.w *= d;
        __nv_bfloat16 h0 = __float2bfloat16_rn(v.x);
        __nv_bfloat16 h1 = __float2bfloat16_rn(v.y);
        __nv_bfloat16 h2 = __float2bfloat16_rn(v.z);
        __nv_bfloat16 h3 = __float2bfloat16_rn(v.w);
        __nv_bfloat16 l0 = __float2bfloat16_rn(v.x - __bfloat162float(h0));
        __nv_bfloat16 l1 = __float2bfloat16_rn(v.y - __bfloat162float(h1));
        __nv_bfloat16 l2 = __float2bfloat16_rn(v.z - __bfloat162float(h2));
        __nv_bfloat16 l3 = __float2bfloat16_rn(v.w - __bfloat162float(h3));
        ushort4 hh, ll;
        hh.x = *(unsigned short*)&h0; hh.y = *(unsigned short*)&h1;
        hh.z = *(unsigned short*)&h2; hh.w = *(unsigned short*)&h3;
        ll.x = *(unsigned short*)&l0; ll.y = *(unsigned short*)&l1;
        ll.z = *(unsigned short*)&l2; ll.w = *(unsigned short*)&l3;
        *(ushort4*)(o + j * 4)      = hh;
        *(ushort4*)(o + 64 + j * 4) = ll;
    }
}

// ---------------- fused diffusion mma + FC + instance-norm + relu ----------------
__global__ void __launch_bounds__(128) k_mm(int layer, float* __restrict__ out_final,
                                            const float* __restrict__ W) {
    __shared__ union {
        unsigned short bs[2][64][SP];
        struct { float lxs[64][68]; float ws[64][64]; } e;
    } SM;

    int b = blockIdx.y, n0 = blockIdx.x * 64;
    int t = threadIdx.x, wr = t >> 5, lane = t & 31;
    int g = lane >> 2, tq = lane & 3;
    int rl8 = (lane & 7) + ((lane >> 3) & 1) * 8;
    int fg = (lane >> 4) * 8;

    const unsigned short* xsrc = (layer == 0) ? g_xs : g_xs2;
    const unsigned short* xsb = xsrc + (size_t)b * NNODE * 128;
    const unsigned* pa = g_adjT + (size_t)b * 128 * NNODE + (n0 + wr * 16 + g);
    const unsigned* pa8 = pa + 8;

    float cc[16][4];
    #pragma unroll
    for (int j = 0; j < 16; j++)
        #pragma unroll
        for (int q = 0; q < 4; q++) cc[j][q] = 0.f;

    int srow = t >> 4, schk = t & 15;
    uint sb0 = (uint)__cvta_generic_to_shared(&SM.bs[0][0][0]);
    uint sb1 = (uint)__cvta_generic_to_shared(&SM.bs[1][0][0]);

    float4 pf[8];
    #pragma unroll
    for (int ps = 0; ps < 8; ps++)
        pf[ps] = *(const float4*)(xsb + (size_t)(srow + ps * 8) * 128 + schk * 8);
    #pragma unroll
    for (int ps = 0; ps < 8; ps++)
        *(float4*)&SM.bs[0][srow + ps * 8][schk * 8] = pf[ps];
    #pragma unroll
    for (int ps = 0; ps < 8; ps++)
        pf[ps] = *(const float4*)(xsb + (size_t)(64 + srow + ps * 8) * 128 + schk * 8);
    unsigned w0a = pa[0], w1a = pa[(size_t)4096];
    unsigned w0b = pa8[0], w1b = pa8[(size_t)4096];

    for (int c = 0; c < 64; c++) {
        __syncthreads();
        if (c + 1 < 64) {
            #pragma unroll
            for (int ps = 0; ps < 8; ps++)
                *(float4*)&SM.bs[(c + 1) & 1][srow + ps * 8][schk * 8] = pf[ps];
            if (c + 2 < 64) {
                #pragma unroll
                for (int ps = 0; ps < 8; ps++)
                    pf[ps] = *(const float4*)(xsb + (size_t)((c + 2) * 64 + srow + ps * 8) * 128 + schk * 8);
            }
        }
        unsigned nw0a = 0, nw1a = 0, nw0b = 0, nw1b = 0;
        if (c + 1 < 64) {
            nw0a = pa[(size_t)(2 * c + 2) * 4096];
            nw1a = pa[(size_t)(2 * c + 3) * 4096];
            nw0b = pa8[(size_t)(2 * c + 2) * 4096];
            nw1b = pa8[(size_t)(2 * c + 3) * 4096];
        }
        uint bb = (c & 1) ? sb1 : sb0;
        #pragma unroll
        for (int q = 0; q < 4; q++) {
            unsigned wA = (q < 2) ? w0a : w1a;
            unsigned wB = (q < 2) ? w0b : w1b;
            int s = ((q & 1) << 4) + 2 * tq;
            uint a0 = bfpair((wA >> s) & 3u);
            uint a2 = bfpair((wA >> (s + 8)) & 3u);
            uint a1 = bfpair((wB >> s) & 3u);
            uint a3 = bfpair((wB >> (s + 8)) & 3u);
            uint baddr = bb + (uint)(((q * 16 + rl8) * SP + fg) * 2);
            #pragma unroll
            for (int p = 0; p < 8; p++) {
                uint r0, r1, r2, r3;
                asm volatile(
                    "ldmatrix.sync.aligned.m8n8.x4.trans.shared.b16 {%0,%1,%2,%3}, [%4];"
                    : "=r"(r0), "=r"(r1), "=r"(r2), "=r"(r3)
                    : "r"(baddr + (uint)(p * 32)));
                MMA_BF16(cc[2 * p],     a0, a1, a2, a3, r0, r1);
                MMA_BF16(cc[2 * p + 1], a0, a1, a2, a3, r2, r3);
            }
        }
        w0a = nw0a; w1a = nw1a; w0b = nw0b; w1b = nw1b;
    }
    __syncthreads();

    {
        int lr0 = wr * 16 + g;
        float dn0 = g_dinv[b * NNODE + n0 + lr0];
        float dn1 = g_dinv[b * NNODE + n0 + lr0 + 8];
        #pragma unroll
        for (int j = 0; j < 8; j++) {
            int col = j * 8 + 2 * tq;
            float2 u0 = make_float2((cc[j][0] + cc[j + 8][0]) * dn0,
                                    (cc[j][1] + cc[j + 8][1]) * dn0);
            float2 u1 = make_float2((cc[j][2] + cc[j + 8][2]) * dn1,
                                    (cc[j][3] + cc[j + 8][3]) * dn1);
            *(float2*)&SM.e.lxs[lr0][col]     = u0;
            *(float2*)&SM.e.lxs[lr0 + 8][col] = u1;
        }
    }
    {
        int c2 = t >> 1, fh = (t & 1) * 32;
        #pragma unroll
        for (int j = 0; j < 8; j++)
            *(float4*)&SM.e.ws[c2][fh + j * 4] = *(const float4*)(W + c2 * 64 + fh + j * 4);
    }
    __syncthreads();

    int row = t >> 1, fh = (t & 1) * 32;
    ull h[16];
    #pragma unroll
    for (int j = 0; j < 16; j++) h[j] = 0ULL;
    #pragma unroll 8
    for (int c = 0; c < 64; c++) {
        ull a2 = pack2(SM.e.lxs[row][c]);
        const ulonglong2* w2 = (const ulonglong2*)&SM.e.ws[c][fh];
        #pragma unroll
        for (int j = 0; j < 4; j++) {
            ulonglong2 u0 = w2[2 * j];
            ulonglong2 u1 = w2[2 * j + 1];
            fma2(h[4 * j],     a2, u0.x);
            fma2(h[4 * j + 1], a2, u0.y);
            fma2(h[4 * j + 2], a2, u1.x);
            fma2(h[4 * j + 3], a2, u1.y);
        }
    }
    float hv[32];
    #pragma unroll
    for (int j = 0; j < 16; j++) { F2U u; u.u = h[j]; hv[2 * j] = u.f.x; hv[2 * j + 1] = u.f.y; }

    float sum = 0.f;
    #pragma unroll
    for (int j = 0; j < 32; j++) sum += hv[j];
    sum += __shfl_xor_sync(0xffffffffu, sum, 1);
    float mean = sum * (1.f / 64.f);
    float vq = 0.f;
    #pragma unroll
    for (int j = 0; j < 32; j++) { float d = hv[j] - mean; vq += d * d; }
    vq += __shfl_xor_sync(0xffffffffu, vq, 1);
    float inv = 1.0f / sqrtf(vq * (1.f / 64.f) + EPSI);

    int gnode = b * NNODE + n0 + row;
    if (layer == 0) {
        float d = g_dinv[gnode];
        unsigned short* o = g_xs2 + (size_t)gnode * 128 + fh;
        #pragma unroll
        for (int f4 = 0; f4 < 8; f4++) {
            ushort4 hh, ll;
            unsigned short* hp = &hh.x;
            unsigned short* lp = &ll.x;
            #pragma unroll
            for (int q = 0; q < 4; q++) {
                float y = fmaxf((hv[f4 * 4 + q] - mean) * inv, 0.f) * d;
                __nv_bfloat16 hb = __float2bfloat16_rn(y);
                __nv_bfloat16 lb = __float2bfloat16_rn(y - __bfloat162float(hb));
                hp[q] = *(unsigned short*)&hb;
                lp[q] = *(unsigned short*)&lb;
            }
            *(ushort4*)(o + f4 * 4)      = hh;
            *(ushort4*)(o + 64 + f4 * 4) = ll;
        }
    } else {
        float* op = out_final + (size_t)gnode * 64 + fh;
        #pragma unroll
        for (int f4 = 0; f4 < 8; f4++) {
            float4 ov;
            ov.x = fmaxf((hv[f4 * 4 + 0] - mean) * inv, 0.f);
            ov.y = fmaxf((hv[f4 * 4 + 1] - mean) * inv, 0.f);
            ov.z = fmaxf((hv[f4 * 4 + 2] - mean) * inv, 0.f);
            ov.w = fmaxf((hv[f4 * 4 + 3] - mean) * inv, 0.f);
            *(float4*)(op + f4 * 4) = ov;
        }
    }
}

// ---------------- launch ----------------
extern "C" void kernel_launch(void* const* d_in, const int* in_sizes, int n_in,
                              void* d_out, int out_size) {
    const float* x  = (const float*)d_in[0];
    const float* W0 = (const float*)d_in[1];
    const float* W1 = (const float*)d_in[2];
    float* out = (float*)d_out;

    k_prep<<<dim3(64, 4), 256>>>(x);
    k_gram<<<dim3(528, 4), 256>>>();
    k_degsplit<<<512, 128>>>();
    k_mm<<<dim3(64, 4), 128>>>(0, nullptr, W0);
    k_mm<<<dim3(64, 4), 128>>>(1, out, W1);
}